// round 4
// baseline (speedup 1.0000x reference)
#include <cuda_runtime.h>
#include <cstdint>

#define D 128
#define TILE 32
#define NTHREADS 256
#define MAXN 50000

typedef unsigned long long u64;

// scratch: aggregated messages per node
__device__ float g_agg[(size_t)MAXN * D];

__device__ __forceinline__ float frelu(float x) { return x > 0.f ? x : 0.f; }

__device__ __forceinline__ u64 pack2(float lo, float hi) {
    u64 r;
    asm("mov.b64 %0, {%1, %2};" : "=l"(r) : "r"(__float_as_uint(lo)), "r"(__float_as_uint(hi)));
    return r;
}
__device__ __forceinline__ u64 bcast2(float v) {
    u64 r;
    asm("mov.b64 %0, {%1, %1};" : "=l"(r) : "r"(__float_as_uint(v)));
    return r;
}
__device__ __forceinline__ void unpack2(u64 v, float& lo, float& hi) {
    unsigned int l, h;
    asm("mov.b64 {%0, %1}, %2;" : "=r"(l), "=r"(h) : "l"(v));
    lo = __uint_as_float(l);
    hi = __uint_as_float(h);
}
__device__ __forceinline__ void fma2(u64& acc, u64 a, u64 b) {
    asm("fma.rn.f32x2 %0, %1, %2, %0;" : "+l"(acc) : "l"(a), "l"(b));
}

// ---------------------------------------------------------------------------
// init: zero agg, copy coords into output coord region
// ---------------------------------------------------------------------------
__global__ void init_kernel(const float* __restrict__ coords,
                            float* __restrict__ out_coords, int N) {
    int total4 = N * (D / 4);
    for (int i = blockIdx.x * blockDim.x + threadIdx.x; i < total4;
         i += gridDim.x * blockDim.x)
        reinterpret_cast<float4*>(g_agg)[i] = make_float4(0.f, 0.f, 0.f, 0.f);
    int c3 = N * 3;
    for (int i = blockIdx.x * blockDim.x + threadIdx.x; i < c3;
         i += gridDim.x * blockDim.x)
        out_coords[i] = coords[i];
}

// ---------------------------------------------------------------------------
// Retiled micro-GEMM: warp owns 16 j (j0 = wid*16 + jg*4) x ALL 32 rows.
// Lane (jg = lane>>3, eg = lane&7) computes rows {eg, eg+8, eg+16, eg+24}
// x cols {j0..j0+3}. Weight fetch per warp per k = 64B coalesced.
// Activation fetch: one LDS.128 per row-slot per 4 k-steps, conflict-free
// (STRIDE % 8 == 4).
//   acc0[ee] packs (j0, j0+1), acc1[ee] packs (j0+2, j0+3)
// ---------------------------------------------------------------------------
template <int K4, int STRIDE>
__device__ __forceinline__ void mm_warp(const float* __restrict__ s_in,
                                        const float* __restrict__ W,
                                        int eg, int j0,
                                        u64 acc0[4], u64 acc1[4]) {
#pragma unroll 2
    for (int k0 = 0; k0 < K4; ++k0) {
        float4 a4[4];
#pragma unroll
        for (int ee = 0; ee < 4; ++ee)
            a4[ee] = *reinterpret_cast<const float4*>(
                s_in + (eg + 8 * ee) * STRIDE + k0 * 4);
#pragma unroll
        for (int kk = 0; kk < 4; ++kk) {
            ulonglong2 w = __ldg(reinterpret_cast<const ulonglong2*>(
                W + (size_t)(k0 * 4 + kk) * D + j0));
#pragma unroll
            for (int ee = 0; ee < 4; ++ee) {
                u64 ap = bcast2(reinterpret_cast<const float*>(&a4[ee])[kk]);
                fma2(acc0[ee], ap, w.x);
                fma2(acc1[ee], ap, w.y);
            }
        }
    }
}

__device__ __forceinline__ void load_bias2(const float* __restrict__ b, int j0,
                                           u64 acc0[4], u64 acc1[4]) {
    float4 bv = __ldg(reinterpret_cast<const float4*>(b + j0));
    u64 b0 = pack2(bv.x, bv.y), b1 = pack2(bv.z, bv.w);
#pragma unroll
    for (int ee = 0; ee < 4; ++ee) {
        acc0[ee] = b0;
        acc1[ee] = b1;
    }
}

// ---------------------------------------------------------------------------
// edge kernel: 32 edges per block
//   smem: s_ef [32][260] ([h_row|h_col|dist2]); aliased later as s_msg[32][132]
//         s_hid [32][132], s_rel [32][4], s_w [32], s_row int[32]
// ---------------------------------------------------------------------------
#define EF_STRIDE 260
#define HID_STRIDE 132
#define EDGE_SMEM_FLOATS (TILE * EF_STRIDE + TILE * HID_STRIDE + TILE * 4 + TILE)
#define EDGE_SMEM_BYTES (EDGE_SMEM_FLOATS * 4 + TILE * 4)

__global__ void edge_kernel(const float* __restrict__ h,
                            const float* __restrict__ coords,
                            const int* __restrict__ ei,
                            const float* __restrict__ We1, const float* __restrict__ be1,
                            const float* __restrict__ We2, const float* __restrict__ be2,
                            const float* __restrict__ Wc1, const float* __restrict__ bc1,
                            const float* __restrict__ Wc2,
                            float* __restrict__ out_coords,
                            int E) {
    extern __shared__ float smem[];
    float* s_ef = smem;                          // [32][260]
    float* s_hid = smem + TILE * EF_STRIDE;      // [32][132]
    float* s_msg = s_ef;                         // alias, [32][132]
    float* s_rel = s_hid + TILE * HID_STRIDE;    // [32][4]
    float* s_w = s_rel + TILE * 4;               // [32]
    int* s_row = reinterpret_cast<int*>(s_w + TILE);

    const int tid = threadIdx.x;
    const int e_base = blockIdx.x * TILE;

    // per-edge scalars: rel coords, dist2, row index
    if (tid < TILE) {
        int ge = e_base + tid;
        int r = 0, c = 0;
        if (ge < E) {
            r = ei[ge];
            c = ei[E + ge];
        }
        s_row[tid] = r;
        float rx = coords[r * 3 + 0] - coords[c * 3 + 0];
        float ry = coords[r * 3 + 1] - coords[c * 3 + 1];
        float rz = coords[r * 3 + 2] - coords[c * 3 + 2];
        s_rel[tid * 4 + 0] = rx;
        s_rel[tid * 4 + 1] = ry;
        s_rel[tid * 4 + 2] = rz;
        s_ef[tid * EF_STRIDE + 256] = rx * rx + ry * ry + rz * rz;
    }

    // gather h[row], h[col] (float4, coalesced per edge row)
    for (int idx = tid; idx < TILE * 32; idx += NTHREADS) {
        int e = idx >> 5, k4 = idx & 31;
        int ge = e_base + e;
        float4 hr = make_float4(0.f, 0.f, 0.f, 0.f), hc = hr;
        if (ge < E) {
            int r = ei[ge];
            int c = ei[E + ge];
            hr = *reinterpret_cast<const float4*>(h + (size_t)r * D + k4 * 4);
            hc = *reinterpret_cast<const float4*>(h + (size_t)c * D + k4 * 4);
        }
        *reinterpret_cast<float4*>(s_ef + e * EF_STRIDE + k4 * 4) = hr;
        *reinterpret_cast<float4*>(s_ef + e * EF_STRIDE + 128 + k4 * 4) = hc;
    }
    __syncthreads();

    const int lane = tid & 31, wid = tid >> 5;
    const int jg = lane >> 3, eg = lane & 7;
    const int j0 = wid * 16 + jg * 4;

    // ---- layer 1: hid = relu(ef @ We1 + be1), K = 257 (256 + dist2 tail) ----
    {
        u64 acc0[4], acc1[4];
        load_bias2(be1, j0, acc0, acc1);
        mm_warp<64, EF_STRIDE>(s_ef, We1, eg, j0, acc0, acc1);
        // k = 256 tail (dist2 column)
        {
            ulonglong2 w = __ldg(reinterpret_cast<const ulonglong2*>(
                We1 + (size_t)256 * D + j0));
#pragma unroll
            for (int ee = 0; ee < 4; ++ee) {
                u64 ap = bcast2(s_ef[(eg + 8 * ee) * EF_STRIDE + 256]);
                fma2(acc0[ee], ap, w.x);
                fma2(acc1[ee], ap, w.y);
            }
        }
#pragma unroll
        for (int ee = 0; ee < 4; ++ee) {
            float v0, v1, v2, v3;
            unpack2(acc0[ee], v0, v1);
            unpack2(acc1[ee], v2, v3);
            *reinterpret_cast<float4*>(s_hid + (eg + 8 * ee) * HID_STRIDE + j0) =
                make_float4(frelu(v0), frelu(v1), frelu(v2), frelu(v3));
        }
    }
    __syncthreads();

    // ---- layer 2: msg = hid @ We2 + be2, K = 128 (overwrites s_ef region) ----
    {
        u64 acc0[4], acc1[4];
        load_bias2(be2, j0, acc0, acc1);
        mm_warp<32, HID_STRIDE>(s_hid, We2, eg, j0, acc0, acc1);
#pragma unroll
        for (int ee = 0; ee < 4; ++ee) {
            float v0, v1, v2, v3;
            unpack2(acc0[ee], v0, v1);
            unpack2(acc1[ee], v2, v3);
            *reinterpret_cast<float4*>(s_msg + (eg + 8 * ee) * HID_STRIDE + j0) =
                make_float4(v0, v1, v2, v3);
        }
    }
    __syncthreads();

    // zero per-edge coord-weight accumulators
    if (tid < TILE) s_w[tid] = 0.f;
    __syncthreads();

    // ---- coord head: w = relu(msg @ Wc1 + bc1) @ Wc2 ----
    {
        u64 acc0[4], acc1[4];
        load_bias2(bc1, j0, acc0, acc1);
        mm_warp<32, HID_STRIDE>(s_msg, Wc1, eg, j0, acc0, acc1);
        float4 c2 = __ldg(reinterpret_cast<const float4*>(Wc2 + j0));
        float ws[4];
#pragma unroll
        for (int ee = 0; ee < 4; ++ee) {
            float v0, v1, v2, v3;
            unpack2(acc0[ee], v0, v1);
            unpack2(acc1[ee], v2, v3);
            ws[ee] = frelu(v0) * c2.x + frelu(v1) * c2.y +
                     frelu(v2) * c2.z + frelu(v3) * c2.w;
        }
        // reduce over jg (lane bits 3,4): lanes with same eg share edges
#pragma unroll
        for (int off = 8; off <= 16; off <<= 1)
#pragma unroll
            for (int ee = 0; ee < 4; ++ee)
                ws[ee] += __shfl_xor_sync(0xffffffffu, ws[ee], off);
        if (jg == 0) {  // lanes 0..7, one per eg
#pragma unroll
            for (int ee = 0; ee < 4; ++ee)
                atomicAdd(s_w + eg + 8 * ee, ws[ee]);
        }
    }
    __syncthreads();

    // per-edge coord atomics
    if (tid < TILE) {
        int ge = e_base + tid;
        if (ge < E) {
            float w = s_w[tid];
            int r = s_row[tid];
            atomicAdd(out_coords + r * 3 + 0, w * s_rel[tid * 4 + 0]);
            atomicAdd(out_coords + r * 3 + 1, w * s_rel[tid * 4 + 1]);
            atomicAdd(out_coords + r * 3 + 2, w * s_rel[tid * 4 + 2]);
        }
    }

    // ---- message scatter-add (coalesced along feature dim) ----
    for (int idx = tid; idx < TILE * D; idx += NTHREADS) {
        int e = idx >> 7, j = idx & 127;
        if (e_base + e < E)
            atomicAdd(g_agg + (size_t)s_row[e] * D + j, s_msg[e * HID_STRIDE + j]);
    }
}

// ---------------------------------------------------------------------------
// node kernel: h_new = relu([h, agg] @ Wn1 + bn1) @ Wn2 + bn2
// ---------------------------------------------------------------------------
#define NODE_SMEM_BYTES ((TILE * EF_STRIDE + TILE * HID_STRIDE) * 4)

__global__ void node_kernel(const float* __restrict__ h,
                            const float* __restrict__ Wn1, const float* __restrict__ bn1,
                            const float* __restrict__ Wn2, const float* __restrict__ bn2,
                            float* __restrict__ out_h, int N) {
    extern __shared__ float smem[];
    float* s_in = smem;                      // [32][260], cols 0..255
    float* s_hid = smem + TILE * EF_STRIDE;  // [32][132]

    const int tid = threadIdx.x;
    const int r_base = blockIdx.x * TILE;

    for (int idx = tid; idx < TILE * 32; idx += NTHREADS) {
        int e = idx >> 5, k4 = idx & 31;
        int row = r_base + e;
        float4 a = make_float4(0.f, 0.f, 0.f, 0.f), b = a;
        if (row < N) {
            a = *reinterpret_cast<const float4*>(h + (size_t)row * D + k4 * 4);
            b = *reinterpret_cast<const float4*>(g_agg + (size_t)row * D + k4 * 4);
        }
        *reinterpret_cast<float4*>(s_in + e * EF_STRIDE + k4 * 4) = a;
        *reinterpret_cast<float4*>(s_in + e * EF_STRIDE + 128 + k4 * 4) = b;
    }
    __syncthreads();

    const int lane = tid & 31, wid = tid >> 5;
    const int jg = lane >> 3, eg = lane & 7;
    const int j0 = wid * 16 + jg * 4;

    {
        u64 acc0[4], acc1[4];
        load_bias2(bn1, j0, acc0, acc1);
        mm_warp<64, EF_STRIDE>(s_in, Wn1, eg, j0, acc0, acc1);
#pragma unroll
        for (int ee = 0; ee < 4; ++ee) {
            float v0, v1, v2, v3;
            unpack2(acc0[ee], v0, v1);
            unpack2(acc1[ee], v2, v3);
            *reinterpret_cast<float4*>(s_hid + (eg + 8 * ee) * HID_STRIDE + j0) =
                make_float4(frelu(v0), frelu(v1), frelu(v2), frelu(v3));
        }
    }
    __syncthreads();

    {
        u64 acc0[4], acc1[4];
        load_bias2(bn2, j0, acc0, acc1);
        mm_warp<32, HID_STRIDE>(s_hid, Wn2, eg, j0, acc0, acc1);
#pragma unroll
        for (int ee = 0; ee < 4; ++ee) {
            int row = r_base + eg + 8 * ee;
            if (row < N) {
                float v0, v1, v2, v3;
                unpack2(acc0[ee], v0, v1);
                unpack2(acc1[ee], v2, v3);
                *reinterpret_cast<float4*>(out_h + (size_t)row * D + j0) =
                    make_float4(v0, v1, v2, v3);
            }
        }
    }
}

// ---------------------------------------------------------------------------
// launch
// ---------------------------------------------------------------------------
extern "C" void kernel_launch(void* const* d_in, const int* in_sizes, int n_in,
                              void* d_out, int out_size) {
    const float* h = (const float*)d_in[0];
    const float* coords = (const float*)d_in[1];
    const int* ei = (const int*)d_in[2];
    const float* We1 = (const float*)d_in[3];
    const float* be1 = (const float*)d_in[4];
    const float* We2 = (const float*)d_in[5];
    const float* be2 = (const float*)d_in[6];
    const float* Wn1 = (const float*)d_in[7];
    const float* bn1 = (const float*)d_in[8];
    const float* Wn2 = (const float*)d_in[9];
    const float* bn2 = (const float*)d_in[10];
    const float* Wc1 = (const float*)d_in[11];
    const float* bc1 = (const float*)d_in[12];
    const float* Wc2 = (const float*)d_in[13];

    int N = in_sizes[0] / D;
    int E = in_sizes[2] / 2;

    float* out_h = (float*)d_out;
    float* out_coords = out_h + (size_t)N * D;

    cudaFuncSetAttribute(edge_kernel, cudaFuncAttributeMaxDynamicSharedMemorySize,
                         EDGE_SMEM_BYTES);
    cudaFuncSetAttribute(node_kernel, cudaFuncAttributeMaxDynamicSharedMemorySize,
                         NODE_SMEM_BYTES);

    init_kernel<<<1184, 256>>>(coords, out_coords, N);

    int edge_blocks = (E + TILE - 1) / TILE;
    edge_kernel<<<edge_blocks, NTHREADS, EDGE_SMEM_BYTES>>>(
        h, coords, ei, We1, be1, We2, be2, Wc1, bc1, Wc2, out_coords, E);

    int node_blocks = (N + TILE - 1) / TILE;
    node_kernel<<<node_blocks, NTHREADS, NODE_SMEM_BYTES>>>(
        h, Wn1, bn1, Wn2, bn2, out_h, N);
}

// round 5
// speedup vs baseline: 2.4173x; 2.4173x over previous
#include <cuda_runtime.h>
#include <cstdint>

#define D 128
#define TILE 32
#define NTHREADS 256
#define MAXN 50000

#define EF_STRIDE 260
#define HID_STRIDE 132

// static scratch
__device__ float g_P1[(size_t)MAXN * D];   // h @ We1[0:128] + be1
__device__ float g_P2[(size_t)MAXN * D];   // h @ We1[128:256]
__device__ float g_agg[(size_t)MAXN * D];  // sum of hid per node
__device__ float g_deg[MAXN];              // degree (as float)
__device__ float g_Wf[D * D];              // We2 @ Wc1
__device__ float g_bf[D];                  // be2 @ Wc1 + bc1

__device__ __forceinline__ float frelu(float x) { return x > 0.f ? x : 0.f; }

// ---------------------------------------------------------------------------
// prep_weights: Wf = We2 @ Wc1, bf = be2 @ Wc1 + bc1
// ---------------------------------------------------------------------------
__global__ void prep_weights(const float* __restrict__ We2,
                             const float* __restrict__ be2,
                             const float* __restrict__ Wc1,
                             const float* __restrict__ bc1) {
    int k = blockIdx.x;    // row of Wf
    int j = threadIdx.x;   // col
    float acc = 0.f;
#pragma unroll 4
    for (int i = 0; i < D; ++i)
        acc += We2[k * D + i] * Wc1[i * D + j];
    g_Wf[k * D + j] = acc;
    if (k == 0) {
        float b = bc1[j];
#pragma unroll 4
        for (int i = 0; i < D; ++i)
            b += be2[i] * Wc1[i * D + j];
        g_bf[j] = b;
    }
}

// ---------------------------------------------------------------------------
// init: zero agg + deg, copy coords into output coord region
// ---------------------------------------------------------------------------
__global__ void init_kernel(const float* __restrict__ coords,
                            float* __restrict__ out_coords, int N) {
    int total4 = N * (D / 4);
    for (int i = blockIdx.x * blockDim.x + threadIdx.x; i < total4;
         i += gridDim.x * blockDim.x)
        reinterpret_cast<float4*>(g_agg)[i] = make_float4(0.f, 0.f, 0.f, 0.f);
    for (int i = blockIdx.x * blockDim.x + threadIdx.x; i < N;
         i += gridDim.x * blockDim.x)
        g_deg[i] = 0.f;
    int c3 = N * 3;
    for (int i = blockIdx.x * blockDim.x + threadIdx.x; i < c3;
         i += gridDim.x * blockDim.x)
        out_coords[i] = coords[i];
}

// ---------------------------------------------------------------------------
// 4x4 register micro-tile GEMM step (R2-proven tiling)
//   warp: fe = lane (j0 = fe*4 spans all 128 j), eg = warp (e0 = eg*4 rows)
// ---------------------------------------------------------------------------
template <int K, int STRIDE>
__device__ __forceinline__ void mm_tile(const float* __restrict__ s_in,
                                        const float* __restrict__ W,
                                        int e0, int j0, float acc[4][4]) {
#pragma unroll 4
    for (int k = 0; k < K; ++k) {
        float4 w = __ldg(reinterpret_cast<const float4*>(W + (size_t)k * D + j0));
        float a[4];
#pragma unroll
        for (int ee = 0; ee < 4; ++ee) a[ee] = s_in[(e0 + ee) * STRIDE + k];
#pragma unroll
        for (int ee = 0; ee < 4; ++ee) {
            acc[ee][0] += a[ee] * w.x;
            acc[ee][1] += a[ee] * w.y;
            acc[ee][2] += a[ee] * w.z;
            acc[ee][3] += a[ee] * w.w;
        }
    }
}

__device__ __forceinline__ void load_bias(const float* __restrict__ b, int j0,
                                          float acc[4][4]) {
    float4 bv = __ldg(reinterpret_cast<const float4*>(b + j0));
#pragma unroll
    for (int ee = 0; ee < 4; ++ee) {
        acc[ee][0] = bv.x; acc[ee][1] = bv.y; acc[ee][2] = bv.z; acc[ee][3] = bv.w;
    }
}

// ---------------------------------------------------------------------------
// node_prep: P1 = h @ We1[0:128] + be1 ; P2 = h @ We1[128:256]
// ---------------------------------------------------------------------------
__global__ void node_prep(const float* __restrict__ h,
                          const float* __restrict__ We1,
                          const float* __restrict__ be1, int N) {
    __shared__ float s_in[TILE * HID_STRIDE];  // 32 x 132, cols 0:128 = h row

    const int tid = threadIdx.x;
    const int r_base = blockIdx.x * TILE;

    for (int idx = tid; idx < TILE * 32; idx += NTHREADS) {
        int e = idx >> 5, k4 = idx & 31;
        int row = r_base + e;
        float4 a = make_float4(0.f, 0.f, 0.f, 0.f);
        if (row < N)
            a = *reinterpret_cast<const float4*>(h + (size_t)row * D + k4 * 4);
        *reinterpret_cast<float4*>(s_in + e * HID_STRIDE + k4 * 4) = a;
    }
    __syncthreads();

    const int fe = tid & 31, eg = tid >> 5;
    const int j0 = fe * 4, e0 = eg * 4;

    {
        float acc[4][4];
        load_bias(be1, j0, acc);
        mm_tile<128, HID_STRIDE>(s_in, We1, e0, j0, acc);
#pragma unroll
        for (int ee = 0; ee < 4; ++ee) {
            int row = r_base + e0 + ee;
            if (row < N)
                *reinterpret_cast<float4*>(g_P1 + (size_t)row * D + j0) =
                    make_float4(acc[ee][0], acc[ee][1], acc[ee][2], acc[ee][3]);
        }
    }
    {
        float acc[4][4];
#pragma unroll
        for (int ee = 0; ee < 4; ++ee)
#pragma unroll
            for (int jj = 0; jj < 4; ++jj) acc[ee][jj] = 0.f;
        mm_tile<128, HID_STRIDE>(s_in, We1 + (size_t)128 * D, e0, j0, acc);
#pragma unroll
        for (int ee = 0; ee < 4; ++ee) {
            int row = r_base + e0 + ee;
            if (row < N)
                *reinterpret_cast<float4*>(g_P2 + (size_t)row * D + j0) =
                    make_float4(acc[ee][0], acc[ee][1], acc[ee][2], acc[ee][3]);
        }
    }
}

// ---------------------------------------------------------------------------
// edge kernel: 32 edges/block.
//   hid = relu(P1[row] + P2[col] + dist2 * We1[256])       (gather + add)
//   w   = relu(hid @ Wf + bf) . Wc2                        (one K=128 GEMM)
//   scatter: g_agg += hid ; deg += 1 ; coords += w*rel
// ---------------------------------------------------------------------------
__global__ void edge_kernel(const float* __restrict__ coords,
                            const int* __restrict__ ei,
                            const float* __restrict__ We1,
                            const float* __restrict__ Wc2,
                            float* __restrict__ out_coords,
                            int E) {
    __shared__ float s_hid[TILE * HID_STRIDE];  // 32 x 132
    __shared__ float s_rel[TILE * 4];
    __shared__ float s_dist[TILE];
    __shared__ int s_row[TILE];
    __shared__ int s_col[TILE];

    const int tid = threadIdx.x;
    const int e_base = blockIdx.x * TILE;

    if (tid < TILE) {
        int ge = e_base + tid;
        int r = 0, c = 0;
        if (ge < E) {
            r = ei[ge];
            c = ei[E + ge];
        }
        s_row[tid] = r;
        s_col[tid] = c;
        float rx = coords[r * 3 + 0] - coords[c * 3 + 0];
        float ry = coords[r * 3 + 1] - coords[c * 3 + 1];
        float rz = coords[r * 3 + 2] - coords[c * 3 + 2];
        s_rel[tid * 4 + 0] = rx;
        s_rel[tid * 4 + 1] = ry;
        s_rel[tid * 4 + 2] = rz;
        s_dist[tid] = rx * rx + ry * ry + rz * rz;
    }
    __syncthreads();

    // gather + fuse layer1 (k4 = tid&31 constant per thread -> hoist w256 load)
    {
        const int k4 = tid & 31;
        float4 w4 = __ldg(reinterpret_cast<const float4*>(
            We1 + (size_t)256 * D + k4 * 4));
        for (int idx = tid; idx < TILE * 32; idx += NTHREADS) {
            int e = idx >> 5;
            float4 hv = make_float4(0.f, 0.f, 0.f, 0.f);
            if (e_base + e < E) {
                int r = s_row[e], c = s_col[e];
                float4 p1 = *reinterpret_cast<const float4*>(
                    g_P1 + (size_t)r * D + k4 * 4);
                float4 p2 = *reinterpret_cast<const float4*>(
                    g_P2 + (size_t)c * D + k4 * 4);
                float d2 = s_dist[e];
                hv.x = frelu(p1.x + p2.x + d2 * w4.x);
                hv.y = frelu(p1.y + p2.y + d2 * w4.y);
                hv.z = frelu(p1.z + p2.z + d2 * w4.z);
                hv.w = frelu(p1.w + p2.w + d2 * w4.w);
            }
            *reinterpret_cast<float4*>(s_hid + e * HID_STRIDE + k4 * 4) = hv;
        }
    }
    __syncthreads();

    const int fe = tid & 31, eg = tid >> 5;
    const int j0 = fe * 4, e0 = eg * 4;

    // coord head: w = relu(hid @ Wf + bf) . Wc2, warp-reduced
    {
        float acc[4][4];
        load_bias(g_bf, j0, acc);
        mm_tile<128, HID_STRIDE>(s_hid, g_Wf, e0, j0, acc);
        float4 c2 = __ldg(reinterpret_cast<const float4*>(Wc2 + j0));
        float ws[4];
#pragma unroll
        for (int ee = 0; ee < 4; ++ee)
            ws[ee] = frelu(acc[ee][0]) * c2.x + frelu(acc[ee][1]) * c2.y +
                     frelu(acc[ee][2]) * c2.z + frelu(acc[ee][3]) * c2.w;
#pragma unroll
        for (int off = 16; off; off >>= 1)
#pragma unroll
            for (int ee = 0; ee < 4; ++ee)
                ws[ee] += __shfl_xor_sync(0xffffffffu, ws[ee], off);
        if (fe == 0) {
#pragma unroll
            for (int ee = 0; ee < 4; ++ee) {
                int e = e0 + ee;
                if (e_base + e < E) {
                    float w = ws[ee];
                    int r = s_row[e];
                    atomicAdd(out_coords + r * 3 + 0, w * s_rel[e * 4 + 0]);
                    atomicAdd(out_coords + r * 3 + 1, w * s_rel[e * 4 + 1]);
                    atomicAdd(out_coords + r * 3 + 2, w * s_rel[e * 4 + 2]);
                }
            }
        }
    }

    // degree
    if (tid < TILE && e_base + tid < E)
        atomicAdd(g_deg + s_row[tid], 1.0f);

    // scatter hid into g_agg (coalesced over feature dim)
    for (int idx = tid; idx < TILE * D; idx += NTHREADS) {
        int e = idx >> 7, j = idx & 127;
        if (e_base + e < E)
            atomicAdd(g_agg + (size_t)s_row[e] * D + j, s_hid[e * HID_STRIDE + j]);
    }
}

// ---------------------------------------------------------------------------
// node kernel:
//   agg_m = g_agg[n] @ We2 + deg[n]*be2
//   h_new = relu([h, agg_m] @ Wn1 + bn1) @ Wn2 + bn2
// ---------------------------------------------------------------------------
#define NODE_SMEM_BYTES ((TILE * EF_STRIDE + TILE * HID_STRIDE + TILE) * 4)

__global__ void node_kernel(const float* __restrict__ h,
                            const float* __restrict__ We2,
                            const float* __restrict__ be2,
                            const float* __restrict__ Wn1, const float* __restrict__ bn1,
                            const float* __restrict__ Wn2, const float* __restrict__ bn2,
                            float* __restrict__ out_h, int N) {
    extern __shared__ float smem[];
    float* s_in = smem;                      // [32][260]: cols 0:128 h, 128:256 agg_m
    float* s_hid = smem + TILE * EF_STRIDE;  // [32][132]
    float* s_deg = s_hid + TILE * HID_STRIDE;  // [32]

    const int tid = threadIdx.x;
    const int r_base = blockIdx.x * TILE;

    // stage h -> s_in[:,0:128], g_agg -> s_hid (temp)
    for (int idx = tid; idx < TILE * 32; idx += NTHREADS) {
        int e = idx >> 5, k4 = idx & 31;
        int row = r_base + e;
        float4 a = make_float4(0.f, 0.f, 0.f, 0.f), b = a;
        if (row < N) {
            a = *reinterpret_cast<const float4*>(h + (size_t)row * D + k4 * 4);
            b = *reinterpret_cast<const float4*>(g_agg + (size_t)row * D + k4 * 4);
        }
        *reinterpret_cast<float4*>(s_in + e * EF_STRIDE + k4 * 4) = a;
        *reinterpret_cast<float4*>(s_hid + e * HID_STRIDE + k4 * 4) = b;
    }
    if (tid < TILE) {
        int row = r_base + tid;
        s_deg[tid] = (row < N) ? g_deg[row] : 0.f;
    }
    __syncthreads();

    const int fe = tid & 31, eg = tid >> 5;
    const int j0 = fe * 4, e0 = eg * 4;

    // agg_m = s_hid @ We2 + deg*be2 -> s_in[:,128:256]
    {
        float acc[4][4];
        float4 b2 = __ldg(reinterpret_cast<const float4*>(be2 + j0));
#pragma unroll
        for (int ee = 0; ee < 4; ++ee) {
            float dg = s_deg[e0 + ee];
            acc[ee][0] = dg * b2.x; acc[ee][1] = dg * b2.y;
            acc[ee][2] = dg * b2.z; acc[ee][3] = dg * b2.w;
        }
        mm_tile<128, HID_STRIDE>(s_hid, We2, e0, j0, acc);
        __syncthreads();  // s_hid fully read before overwrite below
#pragma unroll
        for (int ee = 0; ee < 4; ++ee)
            *reinterpret_cast<float4*>(s_in + (e0 + ee) * EF_STRIDE + 128 + j0) =
                make_float4(acc[ee][0], acc[ee][1], acc[ee][2], acc[ee][3]);
    }
    __syncthreads();

    // layer n1
    {
        float acc[4][4];
        load_bias(bn1, j0, acc);
        mm_tile<256, EF_STRIDE>(s_in, Wn1, e0, j0, acc);
#pragma unroll
        for (int ee = 0; ee < 4; ++ee)
            *reinterpret_cast<float4*>(s_hid + (e0 + ee) * HID_STRIDE + j0) =
                make_float4(frelu(acc[ee][0]), frelu(acc[ee][1]),
                            frelu(acc[ee][2]), frelu(acc[ee][3]));
    }
    __syncthreads();

    // layer n2 -> out
    {
        float acc[4][4];
        load_bias(bn2, j0, acc);
        mm_tile<128, HID_STRIDE>(s_hid, Wn2, e0, j0, acc);
#pragma unroll
        for (int ee = 0; ee < 4; ++ee) {
            int row = r_base + e0 + ee;
            if (row < N)
                *reinterpret_cast<float4*>(out_h + (size_t)row * D + j0) =
                    make_float4(acc[ee][0], acc[ee][1], acc[ee][2], acc[ee][3]);
        }
    }
}

// ---------------------------------------------------------------------------
// launch
// ---------------------------------------------------------------------------
extern "C" void kernel_launch(void* const* d_in, const int* in_sizes, int n_in,
                              void* d_out, int out_size) {
    const float* h = (const float*)d_in[0];
    const float* coords = (const float*)d_in[1];
    const int* ei = (const int*)d_in[2];
    const float* We1 = (const float*)d_in[3];
    const float* be1 = (const float*)d_in[4];
    const float* We2 = (const float*)d_in[5];
    const float* be2 = (const float*)d_in[6];
    const float* Wn1 = (const float*)d_in[7];
    const float* bn1 = (const float*)d_in[8];
    const float* Wn2 = (const float*)d_in[9];
    const float* bn2 = (const float*)d_in[10];
    const float* Wc1 = (const float*)d_in[11];
    const float* bc1 = (const float*)d_in[12];
    const float* Wc2 = (const float*)d_in[13];

    int N = in_sizes[0] / D;
    int E = in_sizes[2] / 2;

    float* out_h = (float*)d_out;
    float* out_coords = out_h + (size_t)N * D;

    cudaFuncSetAttribute(node_kernel, cudaFuncAttributeMaxDynamicSharedMemorySize,
                         NODE_SMEM_BYTES);

    prep_weights<<<D, D>>>(We2, be2, Wc1, bc1);
    node_prep<<<(N + TILE - 1) / TILE, NTHREADS>>>(h, We1, be1, N);
    init_kernel<<<1184, 256>>>(coords, out_coords, N);

    edge_kernel<<<(E + TILE - 1) / TILE, NTHREADS>>>(coords, ei, We1, Wc2,
                                                     out_coords, E);

    node_kernel<<<(N + TILE - 1) / TILE, NTHREADS, NODE_SMEM_BYTES>>>(
        h, We2, be2, Wn1, bn1, Wn2, bn2, out_h, N);
}

// round 7
// speedup vs baseline: 2.5691x; 1.0628x over previous
#include <cuda_runtime.h>
#include <cuda_bf16.h>
#include <cstdint>

#define D 128
#define TILE 32
#define NTHREADS 256
#define MAXN 50000
#define ETILE 64
#define A_STRIDE 136
#define HID_STRIDE 132
#define EF_STRIDE 260

// ---------------------------------------------------------------------------
// static scratch
// ---------------------------------------------------------------------------
__device__ float g_P1[(size_t)MAXN * D];   // h @ We1[0:128] + be1
__device__ float g_P2[(size_t)MAXN * D];   // h @ We1[128:256]
__device__ float g_agg[(size_t)MAXN * D];  // sum of hid per node
__device__ float g_deg[MAXN];              // degree (as float)
__device__ float g_bf[D];                  // be2 @ Wc1 + bc1
// WfT = (We2 @ Wc1)^T  [n][k] row-major, bf16 hi/lo
__device__ __nv_bfloat16 g_WfT_hi[D * D];
__device__ __nv_bfloat16 g_WfT_lo[D * D];

__device__ __forceinline__ float frelu(float x) { return x > 0.f ? x : 0.f; }

__device__ __forceinline__ uint32_t smem_u32(const void* p) {
    uint32_t a;
    asm("{ .reg .u64 t; cvta.to.shared.u64 t, %1; cvt.u32.u64 %0, t; }"
        : "=r"(a) : "l"(p));
    return a;
}

__device__ __forceinline__ void ldmat_x4(uint32_t& a0, uint32_t& a1,
                                         uint32_t& a2, uint32_t& a3,
                                         uint32_t addr) {
    asm volatile(
        "ldmatrix.sync.aligned.m8n8.x4.shared.b16 {%0,%1,%2,%3}, [%4];"
        : "=r"(a0), "=r"(a1), "=r"(a2), "=r"(a3) : "r"(addr));
}

__device__ __forceinline__ void mma_bf16(float d[4], uint32_t a0, uint32_t a1,
                                         uint32_t a2, uint32_t a3,
                                         uint32_t b0, uint32_t b1) {
    asm volatile(
        "mma.sync.aligned.m16n8k16.row.col.f32.bf16.bf16.f32 "
        "{%0,%1,%2,%3}, {%4,%5,%6,%7}, {%8,%9}, {%0,%1,%2,%3};"
        : "+f"(d[0]), "+f"(d[1]), "+f"(d[2]), "+f"(d[3])
        : "r"(a0), "r"(a1), "r"(a2), "r"(a3), "r"(b0), "r"(b1));
}

// ---------------------------------------------------------------------------
// prep_weights: WfT = (We2 @ Wc1)^T -> bf16 hi/lo row-major [n][k]; bf vector
// ---------------------------------------------------------------------------
__global__ void prep_weights(const float* __restrict__ We2,
                             const float* __restrict__ be2,
                             const float* __restrict__ Wc1,
                             const float* __restrict__ bc1) {
    int k = blockIdx.x;   // K index (row of Wf)
    int j = threadIdx.x;  // output col (n)
    float acc = 0.f;
#pragma unroll 4
    for (int i = 0; i < D; ++i)
        acc += We2[k * D + i] * Wc1[i * D + j];
    __nv_bfloat16 hi = __float2bfloat16(acc);
    __nv_bfloat16 lo = __float2bfloat16(acc - __bfloat162float(hi));
    g_WfT_hi[j * D + k] = hi;
    g_WfT_lo[j * D + k] = lo;
    if (k == 0) {
        float b = bc1[j];
#pragma unroll 4
        for (int i = 0; i < D; ++i)
            b += be2[i] * Wc1[i * D + j];
        g_bf[j] = b;
    }
}

// ---------------------------------------------------------------------------
// init: zero agg + deg, copy coords into output coord region
// ---------------------------------------------------------------------------
__global__ void init_kernel(const float* __restrict__ coords,
                            float* __restrict__ out_coords, int N) {
    int total4 = N * (D / 4);
    for (int i = blockIdx.x * blockDim.x + threadIdx.x; i < total4;
         i += gridDim.x * blockDim.x)
        reinterpret_cast<float4*>(g_agg)[i] = make_float4(0.f, 0.f, 0.f, 0.f);
    for (int i = blockIdx.x * blockDim.x + threadIdx.x; i < N;
         i += gridDim.x * blockDim.x)
        g_deg[i] = 0.f;
    int c3 = N * 3;
    for (int i = blockIdx.x * blockDim.x + threadIdx.x; i < c3;
         i += gridDim.x * blockDim.x)
        out_coords[i] = coords[i];
}

// ---------------------------------------------------------------------------
// scalar micro-tile GEMM (node side, proven)
// ---------------------------------------------------------------------------
template <int K, int STRIDE>
__device__ __forceinline__ void mm_tile(const float* __restrict__ s_in,
                                        const float* __restrict__ W,
                                        int e0, int j0, float acc[4][4]) {
#pragma unroll 4
    for (int k = 0; k < K; ++k) {
        float4 w = __ldg(reinterpret_cast<const float4*>(W + (size_t)k * D + j0));
        float a[4];
#pragma unroll
        for (int ee = 0; ee < 4; ++ee) a[ee] = s_in[(e0 + ee) * STRIDE + k];
#pragma unroll
        for (int ee = 0; ee < 4; ++ee) {
            acc[ee][0] += a[ee] * w.x;
            acc[ee][1] += a[ee] * w.y;
            acc[ee][2] += a[ee] * w.z;
            acc[ee][3] += a[ee] * w.w;
        }
    }
}

__device__ __forceinline__ void load_bias(const float* __restrict__ b, int j0,
                                          float acc[4][4]) {
    float4 bv = __ldg(reinterpret_cast<const float4*>(b + j0));
#pragma unroll
    for (int ee = 0; ee < 4; ++ee) {
        acc[ee][0] = bv.x; acc[ee][1] = bv.y; acc[ee][2] = bv.z; acc[ee][3] = bv.w;
    }
}

// ---------------------------------------------------------------------------
// node_prep: P1 = h @ We1[0:128] + be1 ; P2 = h @ We1[128:256]
// ---------------------------------------------------------------------------
__global__ void node_prep(const float* __restrict__ h,
                          const float* __restrict__ We1,
                          const float* __restrict__ be1, int N) {
    __shared__ float s_in[TILE * HID_STRIDE];

    const int tid = threadIdx.x;
    const int r_base = blockIdx.x * TILE;

    for (int idx = tid; idx < TILE * 32; idx += NTHREADS) {
        int e = idx >> 5, k4 = idx & 31;
        int row = r_base + e;
        float4 a = make_float4(0.f, 0.f, 0.f, 0.f);
        if (row < N)
            a = *reinterpret_cast<const float4*>(h + (size_t)row * D + k4 * 4);
        *reinterpret_cast<float4*>(s_in + e * HID_STRIDE + k4 * 4) = a;
    }
    __syncthreads();

    const int fe = tid & 31, eg = tid >> 5;
    const int j0 = fe * 4, e0 = eg * 4;

    {
        float acc[4][4];
        load_bias(be1, j0, acc);
        mm_tile<128, HID_STRIDE>(s_in, We1, e0, j0, acc);
#pragma unroll
        for (int ee = 0; ee < 4; ++ee) {
            int row = r_base + e0 + ee;
            if (row < N)
                *reinterpret_cast<float4*>(g_P1 + (size_t)row * D + j0) =
                    make_float4(acc[ee][0], acc[ee][1], acc[ee][2], acc[ee][3]);
        }
    }
    {
        float acc[4][4];
#pragma unroll
        for (int ee = 0; ee < 4; ++ee)
#pragma unroll
            for (int jj = 0; jj < 4; ++jj) acc[ee][jj] = 0.f;
        mm_tile<128, HID_STRIDE>(s_in, We1 + (size_t)128 * D, e0, j0, acc);
#pragma unroll
        for (int ee = 0; ee < 4; ++ee) {
            int row = r_base + e0 + ee;
            if (row < N)
                *reinterpret_cast<float4*>(g_P2 + (size_t)row * D + j0) =
                    make_float4(acc[ee][0], acc[ee][1], acc[ee][2], acc[ee][3]);
        }
    }
}

// ---------------------------------------------------------------------------
// edge kernel: 64 edges/block, coord head via bf16x3 mma.sync
// smem bytes:
// ---------------------------------------------------------------------------
#define OFF_HID 0                                 // f32 [64][132] = 33792
#define OFF_AHI 33792                             // bf16 [64][136] = 17408
#define OFF_ALO 51200                             // bf16 [64][136] = 17408
#define OFF_REL 68608                             // f32 [64][4] = 1024
#define OFF_DIST 69632                            // f32 [64]
#define OFF_W 69888                               // f32 [64]
#define OFF_ROW 70144                             // int [64]
#define OFF_COL 70400                             // int [64]
#define EDGE_SMEM 70656

__global__ void __launch_bounds__(NTHREADS)
edge_kernel(const float* __restrict__ coords,
            const int* __restrict__ ei,
            const float* __restrict__ We1,
            const float* __restrict__ Wc2,
            float* __restrict__ out_coords,
            int E) {
    extern __shared__ char sm[];
    float* s_hid = reinterpret_cast<float*>(sm + OFF_HID);
    float* s_rel = reinterpret_cast<float*>(sm + OFF_REL);
    float* s_dist = reinterpret_cast<float*>(sm + OFF_DIST);
    float* s_w = reinterpret_cast<float*>(sm + OFF_W);
    int* s_row = reinterpret_cast<int*>(sm + OFF_ROW);
    int* s_col = reinterpret_cast<int*>(sm + OFF_COL);

    const uint32_t sbase = smem_u32(sm);
    const int tid = threadIdx.x;
    const int e_base = blockIdx.x * ETILE;

    // scalar phase: per-edge indices, rel coords, dist2; zero s_w
    if (tid < ETILE) {
        int ge = e_base + tid;
        int r = 0, c = 0;
        if (ge < E) {
            r = ei[ge];
            c = ei[E + ge];
            atomicAdd(g_deg + r, 1.0f);
        }
        s_row[tid] = r;
        s_col[tid] = c;
        float rx = coords[r * 3 + 0] - coords[c * 3 + 0];
        float ry = coords[r * 3 + 1] - coords[c * 3 + 1];
        float rz = coords[r * 3 + 2] - coords[c * 3 + 2];
        s_rel[tid * 4 + 0] = rx;
        s_rel[tid * 4 + 1] = ry;
        s_rel[tid * 4 + 2] = rz;
        s_dist[tid] = rx * rx + ry * ry + rz * rz;
        s_w[tid] = 0.f;
    }
    __syncthreads();

    // gather + layer1 fuse: hid = relu(P1[row] + P2[col] + d2*We1[256])
    // write fp32 (scatter) + bf16 hi/lo A tiles (mma)
    {
        const int k4 = tid & 31;  // constant across iterations
        float4 w4 = __ldg(reinterpret_cast<const float4*>(
            We1 + (size_t)256 * D + k4 * 4));
        for (int idx = tid; idx < ETILE * 32; idx += NTHREADS) {
            int e = idx >> 5;
            float4 hv = make_float4(0.f, 0.f, 0.f, 0.f);
            if (e_base + e < E) {
                int r = s_row[e], c = s_col[e];
                float4 p1 = *reinterpret_cast<const float4*>(
                    g_P1 + (size_t)r * D + k4 * 4);
                float4 p2 = *reinterpret_cast<const float4*>(
                    g_P2 + (size_t)c * D + k4 * 4);
                float d2 = s_dist[e];
                hv.x = frelu(p1.x + p2.x + d2 * w4.x);
                hv.y = frelu(p1.y + p2.y + d2 * w4.y);
                hv.z = frelu(p1.z + p2.z + d2 * w4.z);
                hv.w = frelu(p1.w + p2.w + d2 * w4.w);
            }
            *reinterpret_cast<float4*>(s_hid + e * HID_STRIDE + k4 * 4) = hv;

            __nv_bfloat16 hx = __float2bfloat16(hv.x);
            __nv_bfloat16 hy = __float2bfloat16(hv.y);
            __nv_bfloat16 hz = __float2bfloat16(hv.z);
            __nv_bfloat16 hw = __float2bfloat16(hv.w);
            __nv_bfloat162 hp0, hp1, lp0, lp1;
            hp0.x = hx; hp0.y = hy;
            hp1.x = hz; hp1.y = hw;
            lp0.x = __float2bfloat16(hv.x - __bfloat162float(hx));
            lp0.y = __float2bfloat16(hv.y - __bfloat162float(hy));
            lp1.x = __float2bfloat16(hv.z - __bfloat162float(hz));
            lp1.y = __float2bfloat16(hv.w - __bfloat162float(hw));
            size_t boff = ((size_t)e * A_STRIDE + k4 * 4) * 2;
            *reinterpret_cast<__nv_bfloat162*>(sm + OFF_AHI + boff) = hp0;
            *reinterpret_cast<__nv_bfloat162*>(sm + OFF_AHI + boff + 4) = hp1;
            *reinterpret_cast<__nv_bfloat162*>(sm + OFF_ALO + boff) = lp0;
            *reinterpret_cast<__nv_bfloat162*>(sm + OFF_ALO + boff + 4) = lp1;
        }
    }
    __syncthreads();

    // ---- MMA: z = A @ WfT^T in 3 passes (hi*hi + lo*hi + hi*lo) ----
    // warp w owns n-cols [16w, 16w+16); all 4 m-tiles (64 edges)
    const int lane = tid & 31, wid = tid >> 5;
    const int g = lane >> 2, t = lane & 3;
    const int nb = wid * 16;
    const int arow = lane & 15;
    const int acol8 = (lane >> 4) * 8;

    float dacc[4][2][4];
#pragma unroll
    for (int mt = 0; mt < 4; ++mt)
#pragma unroll
        for (int nt = 0; nt < 2; ++nt)
#pragma unroll
            for (int i = 0; i < 4; ++i) dacc[mt][nt][i] = 0.f;

#pragma unroll
    for (int pass = 0; pass < 3; ++pass) {
        const uint32_t abase = (pass == 1) ? (sbase + OFF_ALO) : (sbase + OFF_AHI);
        const __nv_bfloat16* wf = (pass == 2) ? g_WfT_lo : g_WfT_hi;
#pragma unroll
        for (int ks = 0; ks < 8; ++ks) {
            uint32_t b00, b01, b10, b11;
            {
                int col = ks * 16 + t * 2;
                const uint32_t* p0 = reinterpret_cast<const uint32_t*>(
                    wf + (nb + g) * D + col);
                const uint32_t* p1 = reinterpret_cast<const uint32_t*>(
                    wf + (nb + 8 + g) * D + col);
                b00 = __ldg(p0);
                b01 = __ldg(p0 + 4);  // +8 bf16
                b10 = __ldg(p1);
                b11 = __ldg(p1 + 4);
            }
#pragma unroll
            for (int mt = 0; mt < 4; ++mt) {
                uint32_t addr = abase +
                    (uint32_t)((mt * 16 + arow) * (A_STRIDE * 2) +
                               (ks * 16 + acol8) * 2);
                uint32_t a0, a1, a2, a3;
                ldmat_x4(a0, a1, a2, a3, addr);
                mma_bf16(dacc[mt][0], a0, a1, a2, a3, b00, b01);
                mma_bf16(dacc[mt][1], a0, a1, a2, a3, b10, b11);
            }
        }
    }

    // ---- epilogue: w_e = sum_j relu(z_j + bf_j) * Wc2_j ----
    {
        float p[4][2];
#pragma unroll
        for (int mt = 0; mt < 4; ++mt) p[mt][0] = p[mt][1] = 0.f;
#pragma unroll
        for (int nt = 0; nt < 2; ++nt) {
            int j = nb + nt * 8 + t * 2;
            float bf0 = __ldg(g_bf + j), bf1 = __ldg(g_bf + j + 1);
            float w0 = __ldg(Wc2 + j), w1 = __ldg(Wc2 + j + 1);
#pragma unroll
            for (int mt = 0; mt < 4; ++mt) {
                p[mt][0] += frelu(dacc[mt][nt][0] + bf0) * w0 +
                            frelu(dacc[mt][nt][1] + bf1) * w1;
                p[mt][1] += frelu(dacc[mt][nt][2] + bf0) * w0 +
                            frelu(dacc[mt][nt][3] + bf1) * w1;
            }
        }
        // reduce over t (lane bits 0,1)
#pragma unroll
        for (int off = 1; off <= 2; off <<= 1)
#pragma unroll
            for (int mt = 0; mt < 4; ++mt) {
                p[mt][0] += __shfl_xor_sync(0xffffffffu, p[mt][0], off);
                p[mt][1] += __shfl_xor_sync(0xffffffffu, p[mt][1], off);
            }
        if (t == 0) {
#pragma unroll
            for (int mt = 0; mt < 4; ++mt) {
                atomicAdd(s_w + mt * 16 + g, p[mt][0]);
                atomicAdd(s_w + mt * 16 + 8 + g, p[mt][1]);
            }
        }
    }
    __syncthreads();

    // coord atomics (one thread per edge)
    if (tid < ETILE) {
        int ge = e_base + tid;
        if (ge < E) {
            float w = s_w[tid];
            int r = s_row[tid];
            atomicAdd(out_coords + r * 3 + 0, w * s_rel[tid * 4 + 0]);
            atomicAdd(out_coords + r * 3 + 1, w * s_rel[tid * 4 + 1]);
            atomicAdd(out_coords + r * 3 + 2, w * s_rel[tid * 4 + 2]);
        }
    }

    // g_agg scatter (coalesced over feature dim)
    for (int idx = tid; idx < ETILE * D; idx += NTHREADS) {
        int e = idx >> 7, j = idx & 127;
        if (e_base + e < E)
            atomicAdd(g_agg + (size_t)s_row[e] * D + j, s_hid[e * HID_STRIDE + j]);
    }
}

// ---------------------------------------------------------------------------
// node kernel (unchanged, proven):
//   agg_m = g_agg[n] @ We2 + deg[n]*be2
//   h_new = relu([h, agg_m] @ Wn1 + bn1) @ Wn2 + bn2
// ---------------------------------------------------------------------------
#define NODE_SMEM_BYTES ((TILE * EF_STRIDE + TILE * HID_STRIDE + TILE) * 4)

__global__ void node_kernel(const float* __restrict__ h,
                            const float* __restrict__ We2,
                            const float* __restrict__ be2,
                            const float* __restrict__ Wn1, const float* __restrict__ bn1,
                            const float* __restrict__ Wn2, const float* __restrict__ bn2,
                            float* __restrict__ out_h, int N) {
    extern __shared__ float smem[];
    float* s_in = smem;                        // [32][260]
    float* s_hid = smem + TILE * EF_STRIDE;    // [32][132]
    float* s_deg = s_hid + TILE * HID_STRIDE;  // [32]

    const int tid = threadIdx.x;
    const int r_base = blockIdx.x * TILE;

    for (int idx = tid; idx < TILE * 32; idx += NTHREADS) {
        int e = idx >> 5, k4 = idx & 31;
        int row = r_base + e;
        float4 a = make_float4(0.f, 0.f, 0.f, 0.f), b = a;
        if (row < N) {
            a = *reinterpret_cast<const float4*>(h + (size_t)row * D + k4 * 4);
            b = *reinterpret_cast<const float4*>(g_agg + (size_t)row * D + k4 * 4);
        }
        *reinterpret_cast<float4*>(s_in + e * EF_STRIDE + k4 * 4) = a;
        *reinterpret_cast<float4*>(s_hid + e * HID_STRIDE + k4 * 4) = b;
    }
    if (tid < TILE) {
        int row = r_base + tid;
        s_deg[tid] = (row < N) ? g_deg[row] : 0.f;
    }
    __syncthreads();

    const int fe = tid & 31, eg = tid >> 5;
    const int j0 = fe * 4, e0 = eg * 4;

    {
        float acc[4][4];
        float4 b2 = __ldg(reinterpret_cast<const float4*>(be2 + j0));
#pragma unroll
        for (int ee = 0; ee < 4; ++ee) {
            float dg = s_deg[e0 + ee];
            acc[ee][0] = dg * b2.x; acc[ee][1] = dg * b2.y;
            acc[ee][2] = dg * b2.z; acc[ee][3] = dg * b2.w;
        }
        mm_tile<128, HID_STRIDE>(s_hid, We2, e0, j0, acc);
        __syncthreads();
#pragma unroll
        for (int ee = 0; ee < 4; ++ee)
            *reinterpret_cast<float4*>(s_in + (e0 + ee) * EF_STRIDE + 128 + j0) =
                make_float4(acc[ee][0], acc[ee][1], acc[ee][2], acc[ee][3]);
    }
    __syncthreads();

    {
        float acc[4][4];
        load_bias(bn1, j0, acc);
        mm_tile<256, EF_STRIDE>(s_in, Wn1, e0, j0, acc);
#pragma unroll
        for (int ee = 0; ee < 4; ++ee)
            *reinterpret_cast<float4*>(s_hid + (e0 + ee) * HID_STRIDE + j0) =
                make_float4(frelu(acc[ee][0]), frelu(acc[ee][1]),
                            frelu(acc[ee][2]), frelu(acc[ee][3]));
    }
    __syncthreads();

    {
        float acc[4][4];
        load_bias(bn2, j0, acc);
        mm_tile<128, HID_STRIDE>(s_hid, Wn2, e0, j0, acc);
#pragma unroll
        for (int ee = 0; ee < 4; ++ee) {
            int row = r_base + e0 + ee;
            if (row < N)
                *reinterpret_cast<float4*>(out_h + (size_t)row * D + j0) =
                    make_float4(acc[ee][0], acc[ee][1], acc[ee][2], acc[ee][3]);
        }
    }
}

// ---------------------------------------------------------------------------
// launch
// ---------------------------------------------------------------------------
extern "C" void kernel_launch(void* const* d_in, const int* in_sizes, int n_in,
                              void* d_out, int out_size) {
    const float* h = (const float*)d_in[0];
    const float* coords = (const float*)d_in[1];
    const int* ei = (const int*)d_in[2];
    const float* We1 = (const float*)d_in[3];
    const float* be1 = (const float*)d_in[4];
    const float* We2 = (const float*)d_in[5];
    const float* be2 = (const float*)d_in[6];
    const float* Wn1 = (const float*)d_in[7];
    const float* bn1 = (const float*)d_in[8];
    const float* Wn2 = (const float*)d_in[9];
    const float* bn2 = (const float*)d_in[10];
    const float* Wc1 = (const float*)d_in[11];
    const float* bc1 = (const float*)d_in[12];
    const float* Wc2 = (const float*)d_in[13];

    int N = in_sizes[0] / D;
    int E = in_sizes[2] / 2;

    float* out_h = (float*)d_out;
    float* out_coords = out_h + (size_t)N * D;

    cudaFuncSetAttribute(edge_kernel, cudaFuncAttributeMaxDynamicSharedMemorySize,
                         EDGE_SMEM);
    cudaFuncSetAttribute(node_kernel, cudaFuncAttributeMaxDynamicSharedMemorySize,
                         NODE_SMEM_BYTES);

    prep_weights<<<D, D>>>(We2, be2, Wc1, bc1);
    node_prep<<<(N + TILE - 1) / TILE, NTHREADS>>>(h, We1, be1, N);
    init_kernel<<<1184, 256>>>(coords, out_coords, N);

    edge_kernel<<<(E + ETILE - 1) / ETILE, NTHREADS, EDGE_SMEM>>>(
        coords, ei, We1, Wc2, out_coords, E);

    node_kernel<<<(N + TILE - 1) / TILE, NTHREADS, NODE_SMEM_BYTES>>>(
        h, We2, be2, Wn1, bn1, Wn2, bn2, out_h, N);
}

// round 9
// speedup vs baseline: 2.7867x; 1.0847x over previous
#include <cuda_runtime.h>
#include <cuda_bf16.h>
#include <cstdint>

#define D 128
#define TILE 32
#define NTHREADS 256
#define MAXN 50000
#define ETILE 64
#define A_STRIDE 136
#define HID_STRIDE 132
#define EF_STRIDE 260

// ---------------------------------------------------------------------------
// static scratch
// ---------------------------------------------------------------------------
__device__ float g_P1[(size_t)MAXN * D];   // h @ We1[0:128] + be1
__device__ float g_P2[(size_t)MAXN * D];   // h @ We1[128:256]
__device__ float g_agg[(size_t)MAXN * D];  // sum of hid per node
__device__ float g_deg[MAXN];              // degree (as float)
__device__ float g_bf[D];                  // be2 @ Wc1 + bc1
// WfT = (We2 @ Wc1)^T  [n][k] row-major, bf16 hi/lo
__device__ __nv_bfloat16 g_WfT_hi[D * D];
__device__ __nv_bfloat16 g_WfT_lo[D * D];

__device__ __forceinline__ float frelu(float x) { return x > 0.f ? x : 0.f; }

__device__ __forceinline__ uint32_t smem_u32(const void* p) {
    uint32_t a;
    asm("{ .reg .u64 t; cvta.to.shared.u64 t, %1; cvt.u32.u64 %0, t; }"
        : "=r"(a) : "l"(p));
    return a;
}

__device__ __forceinline__ void ldmat_x4(uint32_t& a0, uint32_t& a1,
                                         uint32_t& a2, uint32_t& a3,
                                         uint32_t addr) {
    asm volatile(
        "ldmatrix.sync.aligned.m8n8.x4.shared.b16 {%0,%1,%2,%3}, [%4];"
        : "=r"(a0), "=r"(a1), "=r"(a2), "=r"(a3) : "r"(addr));
}

__device__ __forceinline__ void mma_bf16(float d[4], uint32_t a0, uint32_t a1,
                                         uint32_t a2, uint32_t a3,
                                         uint32_t b0, uint32_t b1) {
    asm volatile(
        "mma.sync.aligned.m16n8k16.row.col.f32.bf16.bf16.f32 "
        "{%0,%1,%2,%3}, {%4,%5,%6,%7}, {%8,%9}, {%0,%1,%2,%3};"
        : "+f"(d[0]), "+f"(d[1]), "+f"(d[2]), "+f"(d[3])
        : "r"(a0), "r"(a1), "r"(a2), "r"(a3), "r"(b0), "r"(b1));
}

// ---------------------------------------------------------------------------
// prep_weights: WfT = (We2 @ Wc1)^T -> bf16 hi/lo row-major [n][k]; bf vector
// ---------------------------------------------------------------------------
__global__ void prep_weights(const float* __restrict__ We2,
                             const float* __restrict__ be2,
                             const float* __restrict__ Wc1,
                             const float* __restrict__ bc1) {
    int k = blockIdx.x;   // K index (row of Wf)
    int j = threadIdx.x;  // output col (n)
    float acc = 0.f;
#pragma unroll 4
    for (int i = 0; i < D; ++i)
        acc += We2[k * D + i] * Wc1[i * D + j];
    __nv_bfloat16 hi = __float2bfloat16(acc);
    __nv_bfloat16 lo = __float2bfloat16(acc - __bfloat162float(hi));
    g_WfT_hi[j * D + k] = hi;
    g_WfT_lo[j * D + k] = lo;
    if (k == 0) {
        float b = bc1[j];
#pragma unroll 4
        for (int i = 0; i < D; ++i)
            b += be2[i] * Wc1[i * D + j];
        g_bf[j] = b;
    }
}

// ---------------------------------------------------------------------------
// init: zero agg + deg, copy coords into output coord region
// ---------------------------------------------------------------------------
__global__ void init_kernel(const float* __restrict__ coords,
                            float* __restrict__ out_coords, int N) {
    int total4 = N * (D / 4);
    for (int i = blockIdx.x * blockDim.x + threadIdx.x; i < total4;
         i += gridDim.x * blockDim.x)
        reinterpret_cast<float4*>(g_agg)[i] = make_float4(0.f, 0.f, 0.f, 0.f);
    for (int i = blockIdx.x * blockDim.x + threadIdx.x; i < N;
         i += gridDim.x * blockDim.x)
        g_deg[i] = 0.f;
    int c3 = N * 3;
    for (int i = blockIdx.x * blockDim.x + threadIdx.x; i < c3;
         i += gridDim.x * blockDim.x)
        out_coords[i] = coords[i];
}

// ---------------------------------------------------------------------------
// scalar micro-tile GEMM (node side, proven)
// ---------------------------------------------------------------------------
template <int K, int STRIDE>
__device__ __forceinline__ void mm_tile(const float* __restrict__ s_in,
                                        const float* __restrict__ W,
                                        int e0, int j0, float acc[4][4]) {
#pragma unroll 4
    for (int k = 0; k < K; ++k) {
        float4 w = __ldg(reinterpret_cast<const float4*>(W + (size_t)k * D + j0));
        float a[4];
#pragma unroll
        for (int ee = 0; ee < 4; ++ee) a[ee] = s_in[(e0 + ee) * STRIDE + k];
#pragma unroll
        for (int ee = 0; ee < 4; ++ee) {
            acc[ee][0] += a[ee] * w.x;
            acc[ee][1] += a[ee] * w.y;
            acc[ee][2] += a[ee] * w.z;
            acc[ee][3] += a[ee] * w.w;
        }
    }
}

__device__ __forceinline__ void load_bias(const float* __restrict__ b, int j0,
                                          float acc[4][4]) {
    float4 bv = __ldg(reinterpret_cast<const float4*>(b + j0));
#pragma unroll
    for (int ee = 0; ee < 4; ++ee) {
        acc[ee][0] = bv.x; acc[ee][1] = bv.y; acc[ee][2] = bv.z; acc[ee][3] = bv.w;
    }
}

// ---------------------------------------------------------------------------
// node_prep: P1 = h @ We1[0:128] + be1 ; P2 = h @ We1[128:256]
// ---------------------------------------------------------------------------
__global__ void node_prep(const float* __restrict__ h,
                          const float* __restrict__ We1,
                          const float* __restrict__ be1, int N) {
    __shared__ float s_in[TILE * HID_STRIDE];

    const int tid = threadIdx.x;
    const int r_base = blockIdx.x * TILE;

    for (int idx = tid; idx < TILE * 32; idx += NTHREADS) {
        int e = idx >> 5, k4 = idx & 31;
        int row = r_base + e;
        float4 a = make_float4(0.f, 0.f, 0.f, 0.f);
        if (row < N)
            a = *reinterpret_cast<const float4*>(h + (size_t)row * D + k4 * 4);
        *reinterpret_cast<float4*>(s_in + e * HID_STRIDE + k4 * 4) = a;
    }
    __syncthreads();

    const int fe = tid & 31, eg = tid >> 5;
    const int j0 = fe * 4, e0 = eg * 4;

    {
        float acc[4][4];
        load_bias(be1, j0, acc);
        mm_tile<128, HID_STRIDE>(s_in, We1, e0, j0, acc);
#pragma unroll
        for (int ee = 0; ee < 4; ++ee) {
            int row = r_base + e0 + ee;
            if (row < N)
                *reinterpret_cast<float4*>(g_P1 + (size_t)row * D + j0) =
                    make_float4(acc[ee][0], acc[ee][1], acc[ee][2], acc[ee][3]);
        }
    }
    {
        float acc[4][4];
#pragma unroll
        for (int ee = 0; ee < 4; ++ee)
#pragma unroll
            for (int jj = 0; jj < 4; ++jj) acc[ee][jj] = 0.f;
        mm_tile<128, HID_STRIDE>(s_in, We1 + (size_t)128 * D, e0, j0, acc);
#pragma unroll
        for (int ee = 0; ee < 4; ++ee) {
            int row = r_base + e0 + ee;
            if (row < N)
                *reinterpret_cast<float4*>(g_P2 + (size_t)row * D + j0) =
                    make_float4(acc[ee][0], acc[ee][1], acc[ee][2], acc[ee][3]);
        }
    }
}

// ---------------------------------------------------------------------------
// edge kernel: 64 edges/block, coord head via bf16x3 mma.sync.
// Occupancy build: no fp32 hid buffer (scatter fused into gather loop),
// launch_bounds cap at 128 regs -> >=2 CTAs/SM.
// ---------------------------------------------------------------------------
#define OFF_AHI 0                                 // bf16 [64][136] = 17408
#define OFF_ALO 17408                             // bf16 [64][136] = 17408
#define OFF_REL 34816                             // f32 [64][4] = 1024
#define OFF_DIST 35840                            // f32 [64]
#define OFF_W 36096                               // f32 [64]
#define OFF_ROW 36352                             // int [64]
#define OFF_COL 36608                             // int [64]
#define EDGE_SMEM 36864

__global__ void __launch_bounds__(NTHREADS, 2)
edge_kernel(const float* __restrict__ coords,
            const int* __restrict__ ei,
            const float* __restrict__ We1,
            const float* __restrict__ Wc2,
            float* __restrict__ out_coords,
            int E) {
    extern __shared__ char sm[];
    float* s_rel = reinterpret_cast<float*>(sm + OFF_REL);
    float* s_dist = reinterpret_cast<float*>(sm + OFF_DIST);
    float* s_w = reinterpret_cast<float*>(sm + OFF_W);
    int* s_row = reinterpret_cast<int*>(sm + OFF_ROW);
    int* s_col = reinterpret_cast<int*>(sm + OFF_COL);

    const uint32_t sbase = smem_u32(sm);
    const int tid = threadIdx.x;
    const int e_base = blockIdx.x * ETILE;

    // scalar phase: per-edge indices, rel coords, dist2; zero s_w
    if (tid < ETILE) {
        int ge = e_base + tid;
        int r = 0, c = 0;
        if (ge < E) {
            r = ei[ge];
            c = ei[E + ge];
            atomicAdd(g_deg + r, 1.0f);
        }
        s_row[tid] = r;
        s_col[tid] = c;
        float rx = coords[r * 3 + 0] - coords[c * 3 + 0];
        float ry = coords[r * 3 + 1] - coords[c * 3 + 1];
        float rz = coords[r * 3 + 2] - coords[c * 3 + 2];
        s_rel[tid * 4 + 0] = rx;
        s_rel[tid * 4 + 1] = ry;
        s_rel[tid * 4 + 2] = rz;
        s_dist[tid] = rx * rx + ry * ry + rz * rz;
        s_w[tid] = 0.f;
    }
    __syncthreads();

    // gather + layer1 fuse: hid = relu(P1[row] + P2[col] + d2*We1[256]);
    // immediately scatter fp32 hid to g_agg and write bf16 hi/lo A tiles.
    {
        const int k4 = tid & 31;  // constant across iterations
        float4 w4 = __ldg(reinterpret_cast<const float4*>(
            We1 + (size_t)256 * D + k4 * 4));
        for (int idx = tid; idx < ETILE * 32; idx += NTHREADS) {
            int e = idx >> 5;
            float4 hv = make_float4(0.f, 0.f, 0.f, 0.f);
            bool live = (e_base + e < E);
            if (live) {
                int r = s_row[e], c = s_col[e];
                float4 p1 = *reinterpret_cast<const float4*>(
                    g_P1 + (size_t)r * D + k4 * 4);
                float4 p2 = *reinterpret_cast<const float4*>(
                    g_P2 + (size_t)c * D + k4 * 4);
                float d2 = s_dist[e];
                hv.x = frelu(p1.x + p2.x + d2 * w4.x);
                hv.y = frelu(p1.y + p2.y + d2 * w4.y);
                hv.z = frelu(p1.z + p2.z + d2 * w4.z);
                hv.w = frelu(p1.w + p2.w + d2 * w4.w);
                // fused scatter (coalesced over feature dim across the warp)
                float* dst = g_agg + (size_t)r * D + k4 * 4;
                atomicAdd(dst + 0, hv.x);
                atomicAdd(dst + 1, hv.y);
                atomicAdd(dst + 2, hv.z);
                atomicAdd(dst + 3, hv.w);
            }

            __nv_bfloat16 hx = __float2bfloat16(hv.x);
            __nv_bfloat16 hy = __float2bfloat16(hv.y);
            __nv_bfloat16 hz = __float2bfloat16(hv.z);
            __nv_bfloat16 hw = __float2bfloat16(hv.w);
            __nv_bfloat162 hp0, hp1, lp0, lp1;
            hp0.x = hx; hp0.y = hy;
            hp1.x = hz; hp1.y = hw;
            lp0.x = __float2bfloat16(hv.x - __bfloat162float(hx));
            lp0.y = __float2bfloat16(hv.y - __bfloat162float(hy));
            lp1.x = __float2bfloat16(hv.z - __bfloat162float(hz));
            lp1.y = __float2bfloat16(hv.w - __bfloat162float(hw));
            size_t boff = ((size_t)e * A_STRIDE + k4 * 4) * 2;
            *reinterpret_cast<__nv_bfloat162*>(sm + OFF_AHI + boff) = hp0;
            *reinterpret_cast<__nv_bfloat162*>(sm + OFF_AHI + boff + 4) = hp1;
            *reinterpret_cast<__nv_bfloat162*>(sm + OFF_ALO + boff) = lp0;
            *reinterpret_cast<__nv_bfloat162*>(sm + OFF_ALO + boff + 4) = lp1;
        }
    }
    __syncthreads();

    // ---- MMA: z = A @ WfT^T in 3 passes (hi*hi + lo*hi + hi*lo) ----
    // warp w owns n-cols [16w, 16w+16); all 4 m-tiles (64 edges)
    const int lane = tid & 31, wid = tid >> 5;
    const int g = lane >> 2, t = lane & 3;
    const int nb = wid * 16;
    const int arow = lane & 15;
    const int acol8 = (lane >> 4) * 8;

    float dacc[4][2][4];
#pragma unroll
    for (int mt = 0; mt < 4; ++mt)
#pragma unroll
        for (int nt = 0; nt < 2; ++nt)
#pragma unroll
            for (int i = 0; i < 4; ++i) dacc[mt][nt][i] = 0.f;

#pragma unroll
    for (int pass = 0; pass < 3; ++pass) {
        const uint32_t abase = (pass == 1) ? (sbase + OFF_ALO) : (sbase + OFF_AHI);
        const __nv_bfloat16* wf = (pass == 2) ? g_WfT_lo : g_WfT_hi;
#pragma unroll
        for (int ks = 0; ks < 8; ++ks) {
            uint32_t b00, b01, b10, b11;
            {
                int col = ks * 16 + t * 2;
                const uint32_t* p0 = reinterpret_cast<const uint32_t*>(
                    wf + (nb + g) * D + col);
                const uint32_t* p1 = reinterpret_cast<const uint32_t*>(
                    wf + (nb + 8 + g) * D + col);
                b00 = __ldg(p0);
                b01 = __ldg(p0 + 4);  // +8 bf16
                b10 = __ldg(p1);
                b11 = __ldg(p1 + 4);
            }
#pragma unroll
            for (int mt = 0; mt < 4; ++mt) {
                uint32_t addr = abase +
                    (uint32_t)((mt * 16 + arow) * (A_STRIDE * 2) +
                               (ks * 16 + acol8) * 2);
                uint32_t a0, a1, a2, a3;
                ldmat_x4(a0, a1, a2, a3, addr);
                mma_bf16(dacc[mt][0], a0, a1, a2, a3, b00, b01);
                mma_bf16(dacc[mt][1], a0, a1, a2, a3, b10, b11);
            }
        }
    }

    // ---- epilogue: w_e = sum_j relu(z_j + bf_j) * Wc2_j ----
    {
        float p[4][2];
#pragma unroll
        for (int mt = 0; mt < 4; ++mt) p[mt][0] = p[mt][1] = 0.f;
#pragma unroll
        for (int nt = 0; nt < 2; ++nt) {
            int j = nb + nt * 8 + t * 2;
            float bf0 = __ldg(g_bf + j), bf1 = __ldg(g_bf + j + 1);
            float w0 = __ldg(Wc2 + j), w1 = __ldg(Wc2 + j + 1);
#pragma unroll
            for (int mt = 0; mt < 4; ++mt) {
                p[mt][0] += frelu(dacc[mt][nt][0] + bf0) * w0 +
                            frelu(dacc[mt][nt][1] + bf1) * w1;
                p[mt][1] += frelu(dacc[mt][nt][2] + bf0) * w0 +
                            frelu(dacc[mt][nt][3] + bf1) * w1;
            }
        }
        // reduce over t (lane bits 0,1)
#pragma unroll
        for (int off = 1; off <= 2; off <<= 1)
#pragma unroll
            for (int mt = 0; mt < 4; ++mt) {
                p[mt][0] += __shfl_xor_sync(0xffffffffu, p[mt][0], off);
                p[mt][1] += __shfl_xor_sync(0xffffffffu, p[mt][1], off);
            }
        if (t == 0) {
#pragma unroll
            for (int mt = 0; mt < 4; ++mt) {
                atomicAdd(s_w + mt * 16 + g, p[mt][0]);
                atomicAdd(s_w + mt * 16 + 8 + g, p[mt][1]);
            }
        }
    }
    __syncthreads();

    // coord atomics (one thread per edge)
    if (tid < ETILE) {
        int ge = e_base + tid;
        if (ge < E) {
            float w = s_w[tid];
            int r = s_row[tid];
            atomicAdd(out_coords + r * 3 + 0, w * s_rel[tid * 4 + 0]);
            atomicAdd(out_coords + r * 3 + 1, w * s_rel[tid * 4 + 1]);
            atomicAdd(out_coords + r * 3 + 2, w * s_rel[tid * 4 + 2]);
        }
    }
}

// ---------------------------------------------------------------------------
// node kernel (unchanged, proven):
//   agg_m = g_agg[n] @ We2 + deg[n]*be2
//   h_new = relu([h, agg_m] @ Wn1 + bn1) @ Wn2 + bn2
// ---------------------------------------------------------------------------
#define NODE_SMEM_BYTES ((TILE * EF_STRIDE + TILE * HID_STRIDE + TILE) * 4)

__global__ void node_kernel(const float* __restrict__ h,
                            const float* __restrict__ We2,
                            const float* __restrict__ be2,
                            const float* __restrict__ Wn1, const float* __restrict__ bn1,
                            const float* __restrict__ Wn2, const float* __restrict__ bn2,
                            float* __restrict__ out_h, int N) {
    extern __shared__ float smem[];
    float* s_in = smem;                        // [32][260]
    float* s_hid = smem + TILE * EF_STRIDE;    // [32][132]
    float* s_deg = s_hid + TILE * HID_STRIDE;  // [32]

    const int tid = threadIdx.x;
    const int r_base = blockIdx.x * TILE;

    for (int idx = tid; idx < TILE * 32; idx += NTHREADS) {
        int e = idx >> 5, k4 = idx & 31;
        int row = r_base + e;
        float4 a = make_float4(0.f, 0.f, 0.f, 0.f), b = a;
        if (row < N) {
            a = *reinterpret_cast<const float4*>(h + (size_t)row * D + k4 * 4);
            b = *reinterpret_cast<const float4*>(g_agg + (size_t)row * D + k4 * 4);
        }
        *reinterpret_cast<float4*>(s_in + e * EF_STRIDE + k4 * 4) = a;
        *reinterpret_cast<float4*>(s_hid + e * HID_STRIDE + k4 * 4) = b;
    }
    if (tid < TILE) {
        int row = r_base + tid;
        s_deg[tid] = (row < N) ? g_deg[row] : 0.f;
    }
    __syncthreads();

    const int fe = tid & 31, eg = tid >> 5;
    const int j0 = fe * 4, e0 = eg * 4;

    {
        float acc[4][4];
        float4 b2 = __ldg(reinterpret_cast<const float4*>(be2 + j0));
#pragma unroll
        for (int ee = 0; ee < 4; ++ee) {
            float dg = s_deg[e0 + ee];
            acc[ee][0] = dg * b2.x; acc[ee][1] = dg * b2.y;
            acc[ee][2] = dg * b2.z; acc[ee][3] = dg * b2.w;
        }
        mm_tile<128, HID_STRIDE>(s_hid, We2, e0, j0, acc);
        __syncthreads();
#pragma unroll
        for (int ee = 0; ee < 4; ++ee)
            *reinterpret_cast<float4*>(s_in + (e0 + ee) * EF_STRIDE + 128 + j0) =
                make_float4(acc[ee][0], acc[ee][1], acc[ee][2], acc[ee][3]);
    }
    __syncthreads();

    {
        float acc[4][4];
        load_bias(bn1, j0, acc);
        mm_tile<256, EF_STRIDE>(s_in, Wn1, e0, j0, acc);
#pragma unroll
        for (int ee = 0; ee < 4; ++ee)
            *reinterpret_cast<float4*>(s_hid + (e0 + ee) * HID_STRIDE + j0) =
                make_float4(frelu(acc[ee][0]), frelu(acc[ee][1]),
                            frelu(acc[ee][2]), frelu(acc[ee][3]));
    }
    __syncthreads();

    {
        float acc[4][4];
        load_bias(bn2, j0, acc);
        mm_tile<128, HID_STRIDE>(s_hid, Wn2, e0, j0, acc);
#pragma unroll
        for (int ee = 0; ee < 4; ++ee) {
            int row = r_base + e0 + ee;
            if (row < N)
                *reinterpret_cast<float4*>(out_h + (size_t)row * D + j0) =
                    make_float4(acc[ee][0], acc[ee][1], acc[ee][2], acc[ee][3]);
        }
    }
}

// ---------------------------------------------------------------------------
// launch
// ---------------------------------------------------------------------------
extern "C" void kernel_launch(void* const* d_in, const int* in_sizes, int n_in,
                              void* d_out, int out_size) {
    const float* h = (const float*)d_in[0];
    const float* coords = (const float*)d_in[1];
    const int* ei = (const int*)d_in[2];
    const float* We1 = (const float*)d_in[3];
    const float* be1 = (const float*)d_in[4];
    const float* We2 = (const float*)d_in[5];
    const float* be2 = (const float*)d_in[6];
    const float* Wn1 = (const float*)d_in[7];
    const float* bn1 = (const float*)d_in[8];
    const float* Wn2 = (const float*)d_in[9];
    const float* bn2 = (const float*)d_in[10];
    const float* Wc1 = (const float*)d_in[11];
    const float* bc1 = (const float*)d_in[12];
    const float* Wc2 = (const float*)d_in[13];

    int N = in_sizes[0] / D;
    int E = in_sizes[2] / 2;

    float* out_h = (float*)d_out;
    float* out_coords = out_h + (size_t)N * D;

    cudaFuncSetAttribute(edge_kernel, cudaFuncAttributeMaxDynamicSharedMemorySize,
                         EDGE_SMEM);
    cudaFuncSetAttribute(node_kernel, cudaFuncAttributeMaxDynamicSharedMemorySize,
                         NODE_SMEM_BYTES);

    prep_weights<<<D, D>>>(We2, be2, Wc1, bc1);
    node_prep<<<(N + TILE - 1) / TILE, NTHREADS>>>(h, We1, be1, N);
    init_kernel<<<1184, 256>>>(coords, out_coords, N);

    edge_kernel<<<(E + ETILE - 1) / ETILE, NTHREADS, EDGE_SMEM>>>(
        coords, ei, We1, Wc2, out_coords, E);

    node_kernel<<<(N + TILE - 1) / TILE, NTHREADS, NODE_SMEM_BYTES>>>(
        h, We2, be2, Wn1, bn1, Wn2, bn2, out_h, N);
}

// round 10
// speedup vs baseline: 3.6363x; 1.3049x over previous
#include <cuda_runtime.h>
#include <cuda_bf16.h>
#include <cstdint>

#define D 128
#define TILE 32
#define NTHREADS 256
#define MAXN 50000
#define ETILE 64
#define A_STRIDE 136
#define HID_STRIDE 132
#define EF_STRIDE 260

// ---------------------------------------------------------------------------
// static scratch
// ---------------------------------------------------------------------------
__device__ float g_P1[(size_t)MAXN * D];   // h @ We1[0:128] + be1
__device__ float g_P2[(size_t)MAXN * D];   // h @ We1[128:256]
__device__ float g_agg[(size_t)MAXN * D];  // sum of hid per node
__device__ float g_deg[MAXN];              // degree (as float)
__device__ float g_bf[D];                  // be2 @ Wc1 + bc1
// WfT = (We2 @ Wc1)^T  [n][k] row-major, bf16 hi/lo
__device__ __nv_bfloat16 g_WfT_hi[D * D];
__device__ __nv_bfloat16 g_WfT_lo[D * D];
// B fragments in mma order: [hi/lo][nb(8)][ks(8)][lane(32)][4] u32
__device__ uint32_t g_Bfrag[2 * 8 * 8 * 32 * 4];

__device__ __forceinline__ float frelu(float x) { return x > 0.f ? x : 0.f; }

__device__ __forceinline__ uint32_t smem_u32(const void* p) {
    uint32_t a;
    asm("{ .reg .u64 t; cvta.to.shared.u64 t, %1; cvt.u32.u64 %0, t; }"
        : "=r"(a) : "l"(p));
    return a;
}

__device__ __forceinline__ void ldmat_x4(uint32_t& a0, uint32_t& a1,
                                         uint32_t& a2, uint32_t& a3,
                                         uint32_t addr) {
    asm volatile(
        "ldmatrix.sync.aligned.m8n8.x4.shared.b16 {%0,%1,%2,%3}, [%4];"
        : "=r"(a0), "=r"(a1), "=r"(a2), "=r"(a3) : "r"(addr));
}

__device__ __forceinline__ void mma_bf16(float d[4], uint32_t a0, uint32_t a1,
                                         uint32_t a2, uint32_t a3,
                                         uint32_t b0, uint32_t b1) {
    asm volatile(
        "mma.sync.aligned.m16n8k16.row.col.f32.bf16.bf16.f32 "
        "{%0,%1,%2,%3}, {%4,%5,%6,%7}, {%8,%9}, {%0,%1,%2,%3};"
        : "+f"(d[0]), "+f"(d[1]), "+f"(d[2]), "+f"(d[3])
        : "r"(a0), "r"(a1), "r"(a2), "r"(a3), "r"(b0), "r"(b1));
}

__device__ __forceinline__ void red_v4(float* dst, float4 v) {
    asm volatile(
        "red.global.add.v4.f32 [%0], {%1, %2, %3, %4};"
        :: "l"(dst), "f"(v.x), "f"(v.y), "f"(v.z), "f"(v.w) : "memory");
}

// ---------------------------------------------------------------------------
// prep_weights: WfT = (We2 @ Wc1)^T -> bf16 hi/lo row-major [n][k]; bf vector
// ---------------------------------------------------------------------------
__global__ void prep_weights(const float* __restrict__ We2,
                             const float* __restrict__ be2,
                             const float* __restrict__ Wc1,
                             const float* __restrict__ bc1) {
    int k = blockIdx.x;   // K index (row of Wf)
    int j = threadIdx.x;  // output col (n)
    float acc = 0.f;
#pragma unroll 4
    for (int i = 0; i < D; ++i)
        acc += We2[k * D + i] * Wc1[i * D + j];
    __nv_bfloat16 hi = __float2bfloat16(acc);
    __nv_bfloat16 lo = __float2bfloat16(acc - __bfloat162float(hi));
    g_WfT_hi[j * D + k] = hi;
    g_WfT_lo[j * D + k] = lo;
    if (k == 0) {
        float b = bc1[j];
#pragma unroll 4
        for (int i = 0; i < D; ++i)
            b += be2[i] * Wc1[i * D + j];
        g_bf[j] = b;
    }
}

// ---------------------------------------------------------------------------
// prep_frags: repack WfT hi/lo into per-warp mma fragment order so the edge
// kernel's B load is one coalesced LDG.128 per (pass, ks).
// ---------------------------------------------------------------------------
__global__ void prep_frags() {
    int idx = blockIdx.x * blockDim.x + threadIdx.x;  // 0..4095
    if (idx >= 2 * 8 * 8 * 32) return;
    int lane = idx & 31;
    int ks = (idx >> 5) & 7;
    int nbk = (idx >> 8) & 7;
    int p = idx >> 11;
    const __nv_bfloat16* wf = p ? g_WfT_lo : g_WfT_hi;
    int g = lane >> 2, t = lane & 3;
    int col = ks * 16 + t * 2;
    int r0 = nbk * 16 + g, r1 = r0 + 8;
    const uint32_t* p0 = reinterpret_cast<const uint32_t*>(wf + r0 * D + col);
    const uint32_t* p1 = reinterpret_cast<const uint32_t*>(wf + r1 * D + col);
    uint32_t* dst = g_Bfrag + (size_t)idx * 4;
    dst[0] = p0[0];
    dst[1] = p0[4];  // +8 bf16 cols
    dst[2] = p1[0];
    dst[3] = p1[4];
}

// ---------------------------------------------------------------------------
// init: zero agg + deg, copy coords into output coord region
// ---------------------------------------------------------------------------
__global__ void init_kernel(const float* __restrict__ coords,
                            float* __restrict__ out_coords, int N) {
    int total4 = N * (D / 4);
    for (int i = blockIdx.x * blockDim.x + threadIdx.x; i < total4;
         i += gridDim.x * blockDim.x)
        reinterpret_cast<float4*>(g_agg)[i] = make_float4(0.f, 0.f, 0.f, 0.f);
    for (int i = blockIdx.x * blockDim.x + threadIdx.x; i < N;
         i += gridDim.x * blockDim.x)
        g_deg[i] = 0.f;
    int c3 = N * 3;
    for (int i = blockIdx.x * blockDim.x + threadIdx.x; i < c3;
         i += gridDim.x * blockDim.x)
        out_coords[i] = coords[i];
}

// ---------------------------------------------------------------------------
// scalar micro-tile GEMM (node side, proven)
// ---------------------------------------------------------------------------
template <int K, int STRIDE>
__device__ __forceinline__ void mm_tile(const float* __restrict__ s_in,
                                        const float* __restrict__ W,
                                        int e0, int j0, float acc[4][4]) {
#pragma unroll 4
    for (int k = 0; k < K; ++k) {
        float4 w = __ldg(reinterpret_cast<const float4*>(W + (size_t)k * D + j0));
        float a[4];
#pragma unroll
        for (int ee = 0; ee < 4; ++ee) a[ee] = s_in[(e0 + ee) * STRIDE + k];
#pragma unroll
        for (int ee = 0; ee < 4; ++ee) {
            acc[ee][0] += a[ee] * w.x;
            acc[ee][1] += a[ee] * w.y;
            acc[ee][2] += a[ee] * w.z;
            acc[ee][3] += a[ee] * w.w;
        }
    }
}

__device__ __forceinline__ void load_bias(const float* __restrict__ b, int j0,
                                          float acc[4][4]) {
    float4 bv = __ldg(reinterpret_cast<const float4*>(b + j0));
#pragma unroll
    for (int ee = 0; ee < 4; ++ee) {
        acc[ee][0] = bv.x; acc[ee][1] = bv.y; acc[ee][2] = bv.z; acc[ee][3] = bv.w;
    }
}

// ---------------------------------------------------------------------------
// node_prep: P1 = h @ We1[0:128] + be1 ; P2 = h @ We1[128:256]
// ---------------------------------------------------------------------------
__global__ void node_prep(const float* __restrict__ h,
                          const float* __restrict__ We1,
                          const float* __restrict__ be1, int N) {
    __shared__ float s_in[TILE * HID_STRIDE];

    const int tid = threadIdx.x;
    const int r_base = blockIdx.x * TILE;

    for (int idx = tid; idx < TILE * 32; idx += NTHREADS) {
        int e = idx >> 5, k4 = idx & 31;
        int row = r_base + e;
        float4 a = make_float4(0.f, 0.f, 0.f, 0.f);
        if (row < N)
            a = *reinterpret_cast<const float4*>(h + (size_t)row * D + k4 * 4);
        *reinterpret_cast<float4*>(s_in + e * HID_STRIDE + k4 * 4) = a;
    }
    __syncthreads();

    const int fe = tid & 31, eg = tid >> 5;
    const int j0 = fe * 4, e0 = eg * 4;

    {
        float acc[4][4];
        load_bias(be1, j0, acc);
        mm_tile<128, HID_STRIDE>(s_in, We1, e0, j0, acc);
#pragma unroll
        for (int ee = 0; ee < 4; ++ee) {
            int row = r_base + e0 + ee;
            if (row < N)
                *reinterpret_cast<float4*>(g_P1 + (size_t)row * D + j0) =
                    make_float4(acc[ee][0], acc[ee][1], acc[ee][2], acc[ee][3]);
        }
    }
    {
        float acc[4][4];
#pragma unroll
        for (int ee = 0; ee < 4; ++ee)
#pragma unroll
            for (int jj = 0; jj < 4; ++jj) acc[ee][jj] = 0.f;
        mm_tile<128, HID_STRIDE>(s_in, We1 + (size_t)128 * D, e0, j0, acc);
#pragma unroll
        for (int ee = 0; ee < 4; ++ee) {
            int row = r_base + e0 + ee;
            if (row < N)
                *reinterpret_cast<float4*>(g_P2 + (size_t)row * D + j0) =
                    make_float4(acc[ee][0], acc[ee][1], acc[ee][2], acc[ee][3]);
        }
    }
}

// ---------------------------------------------------------------------------
// edge kernel: 64 edges/block, coord head via bf16x3 mma.sync.
// ---------------------------------------------------------------------------
#define OFF_AHI 0                                 // bf16 [64][136] = 17408
#define OFF_ALO 17408                             // bf16 [64][136] = 17408
#define OFF_REL 34816                             // f32 [64][4] = 1024
#define OFF_DIST 35840                            // f32 [64]
#define OFF_W 36096                               // f32 [64]
#define OFF_ROW 36352                             // int [64]
#define OFF_COL 36608                             // int [64]
#define EDGE_SMEM 36864

__global__ void __launch_bounds__(NTHREADS, 2)
edge_kernel(const float* __restrict__ coords,
            const int* __restrict__ ei,
            const float* __restrict__ We1,
            const float* __restrict__ Wc2,
            float* __restrict__ out_coords,
            int E) {
    extern __shared__ char sm[];
    float* s_rel = reinterpret_cast<float*>(sm + OFF_REL);
    float* s_dist = reinterpret_cast<float*>(sm + OFF_DIST);
    float* s_w = reinterpret_cast<float*>(sm + OFF_W);
    int* s_row = reinterpret_cast<int*>(sm + OFF_ROW);
    int* s_col = reinterpret_cast<int*>(sm + OFF_COL);

    const uint32_t sbase = smem_u32(sm);
    const int tid = threadIdx.x;
    const int e_base = blockIdx.x * ETILE;

    // scalar phase: per-edge indices, rel coords, dist2; zero s_w
    if (tid < ETILE) {
        int ge = e_base + tid;
        int r = 0, c = 0;
        if (ge < E) {
            r = ei[ge];
            c = ei[E + ge];
            atomicAdd(g_deg + r, 1.0f);
        }
        s_row[tid] = r;
        s_col[tid] = c;
        float rx = coords[r * 3 + 0] - coords[c * 3 + 0];
        float ry = coords[r * 3 + 1] - coords[c * 3 + 1];
        float rz = coords[r * 3 + 2] - coords[c * 3 + 2];
        s_rel[tid * 4 + 0] = rx;
        s_rel[tid * 4 + 1] = ry;
        s_rel[tid * 4 + 2] = rz;
        s_dist[tid] = rx * rx + ry * ry + rz * rz;
        s_w[tid] = 0.f;
    }
    __syncthreads();

    // gather + layer1 fuse: hid = relu(P1[row] + P2[col] + d2*We1[256]);
    // fused scatter now one contiguous red.v4 per lane (512B/warp).
    {
        const int k4 = tid & 31;  // constant across iterations
        float4 w4 = __ldg(reinterpret_cast<const float4*>(
            We1 + (size_t)256 * D + k4 * 4));
        for (int idx = tid; idx < ETILE * 32; idx += NTHREADS) {
            int e = idx >> 5;
            float4 hv = make_float4(0.f, 0.f, 0.f, 0.f);
            bool live = (e_base + e < E);
            if (live) {
                int r = s_row[e], c = s_col[e];
                float4 p1 = *reinterpret_cast<const float4*>(
                    g_P1 + (size_t)r * D + k4 * 4);
                float4 p2 = *reinterpret_cast<const float4*>(
                    g_P2 + (size_t)c * D + k4 * 4);
                float d2 = s_dist[e];
                hv.x = frelu(p1.x + p2.x + d2 * w4.x);
                hv.y = frelu(p1.y + p2.y + d2 * w4.y);
                hv.z = frelu(p1.z + p2.z + d2 * w4.z);
                hv.w = frelu(p1.w + p2.w + d2 * w4.w);
                red_v4(g_agg + (size_t)r * D + k4 * 4, hv);
            }

            __nv_bfloat16 hx = __float2bfloat16(hv.x);
            __nv_bfloat16 hy = __float2bfloat16(hv.y);
            __nv_bfloat16 hz = __float2bfloat16(hv.z);
            __nv_bfloat16 hw = __float2bfloat16(hv.w);
            __nv_bfloat162 hp0, hp1, lp0, lp1;
            hp0.x = hx; hp0.y = hy;
            hp1.x = hz; hp1.y = hw;
            lp0.x = __float2bfloat16(hv.x - __bfloat162float(hx));
            lp0.y = __float2bfloat16(hv.y - __bfloat162float(hy));
            lp1.x = __float2bfloat16(hv.z - __bfloat162float(hz));
            lp1.y = __float2bfloat16(hv.w - __bfloat162float(hw));
            size_t boff = ((size_t)e * A_STRIDE + k4 * 4) * 2;
            *reinterpret_cast<__nv_bfloat162*>(sm + OFF_AHI + boff) = hp0;
            *reinterpret_cast<__nv_bfloat162*>(sm + OFF_AHI + boff + 4) = hp1;
            *reinterpret_cast<__nv_bfloat162*>(sm + OFF_ALO + boff) = lp0;
            *reinterpret_cast<__nv_bfloat162*>(sm + OFF_ALO + boff + 4) = lp1;
        }
    }
    __syncthreads();

    // ---- MMA: z = A @ WfT^T in 3 passes (hi*hi + lo*hi + hi*lo) ----
    // warp w owns n-cols [16w, 16w+16); all 4 m-tiles (64 edges)
    const int lane = tid & 31, wid = tid >> 5;
    const int g = lane >> 2, t = lane & 3;
    const int nb = wid * 16;
    const int arow = lane & 15;
    const int acol8 = (lane >> 4) * 8;

    float dacc[4][2][4];
#pragma unroll
    for (int mt = 0; mt < 4; ++mt)
#pragma unroll
        for (int nt = 0; nt < 2; ++nt)
#pragma unroll
            for (int i = 0; i < 4; ++i) dacc[mt][nt][i] = 0.f;

#pragma unroll
    for (int pass = 0; pass < 3; ++pass) {
        const uint32_t abase = (pass == 1) ? (sbase + OFF_ALO) : (sbase + OFF_AHI);
        const int psel = (pass == 2) ? 1 : 0;
#pragma unroll
        for (int ks = 0; ks < 8; ++ks) {
            // one coalesced LDG.128 per warp: pre-packed B fragment
            uint4 bv = *reinterpret_cast<const uint4*>(
                g_Bfrag + ((((size_t)psel * 8 + wid) * 8 + ks) * 32 + lane) * 4);
            uint32_t b00 = bv.x, b01 = bv.y, b10 = bv.z, b11 = bv.w;
#pragma unroll
            for (int mt = 0; mt < 4; ++mt) {
                uint32_t addr = abase +
                    (uint32_t)((mt * 16 + arow) * (A_STRIDE * 2) +
                               (ks * 16 + acol8) * 2);
                uint32_t a0, a1, a2, a3;
                ldmat_x4(a0, a1, a2, a3, addr);
                mma_bf16(dacc[mt][0], a0, a1, a2, a3, b00, b01);
                mma_bf16(dacc[mt][1], a0, a1, a2, a3, b10, b11);
            }
        }
    }

    // ---- epilogue: w_e = sum_j relu(z_j + bf_j) * Wc2_j ----
    {
        float p[4][2];
#pragma unroll
        for (int mt = 0; mt < 4; ++mt) p[mt][0] = p[mt][1] = 0.f;
#pragma unroll
        for (int nt = 0; nt < 2; ++nt) {
            int j = nb + nt * 8 + t * 2;
            float bf0 = __ldg(g_bf + j), bf1 = __ldg(g_bf + j + 1);
            float w0 = __ldg(Wc2 + j), w1 = __ldg(Wc2 + j + 1);
#pragma unroll
            for (int mt = 0; mt < 4; ++mt) {
                p[mt][0] += frelu(dacc[mt][nt][0] + bf0) * w0 +
                            frelu(dacc[mt][nt][1] + bf1) * w1;
                p[mt][1] += frelu(dacc[mt][nt][2] + bf0) * w0 +
                            frelu(dacc[mt][nt][3] + bf1) * w1;
            }
        }
        // reduce over t (lane bits 0,1)
#pragma unroll
        for (int off = 1; off <= 2; off <<= 1)
#pragma unroll
            for (int mt = 0; mt < 4; ++mt) {
                p[mt][0] += __shfl_xor_sync(0xffffffffu, p[mt][0], off);
                p[mt][1] += __shfl_xor_sync(0xffffffffu, p[mt][1], off);
            }
        if (t == 0) {
#pragma unroll
            for (int mt = 0; mt < 4; ++mt) {
                atomicAdd(s_w + mt * 16 + g, p[mt][0]);
                atomicAdd(s_w + mt * 16 + 8 + g, p[mt][1]);
            }
        }
    }
    __syncthreads();

    // coord atomics (one thread per edge)
    if (tid < ETILE) {
        int ge = e_base + tid;
        if (ge < E) {
            float w = s_w[tid];
            int r = s_row[tid];
            atomicAdd(out_coords + r * 3 + 0, w * s_rel[tid * 4 + 0]);
            atomicAdd(out_coords + r * 3 + 1, w * s_rel[tid * 4 + 1]);
            atomicAdd(out_coords + r * 3 + 2, w * s_rel[tid * 4 + 2]);
        }
    }
}

// ---------------------------------------------------------------------------
// node kernel (unchanged, proven):
//   agg_m = g_agg[n] @ We2 + deg[n]*be2
//   h_new = relu([h, agg_m] @ Wn1 + bn1) @ Wn2 + bn2
// ---------------------------------------------------------------------------
#define NODE_SMEM_BYTES ((TILE * EF_STRIDE + TILE * HID_STRIDE + TILE) * 4)

__global__ void node_kernel(const float* __restrict__ h,
                            const float* __restrict__ We2,
                            const float* __restrict__ be2,
                            const float* __restrict__ Wn1, const float* __restrict__ bn1,
                            const float* __restrict__ Wn2, const float* __restrict__ bn2,
                            float* __restrict__ out_h, int N) {
    extern __shared__ float smem[];
    float* s_in = smem;                        // [32][260]
    float* s_hid = smem + TILE * EF_STRIDE;    // [32][132]
    float* s_deg = s_hid + TILE * HID_STRIDE;  // [32]

    const int tid = threadIdx.x;
    const int r_base = blockIdx.x * TILE;

    for (int idx = tid; idx < TILE * 32; idx += NTHREADS) {
        int e = idx >> 5, k4 = idx & 31;
        int row = r_base + e;
        float4 a = make_float4(0.f, 0.f, 0.f, 0.f), b = a;
        if (row < N) {
            a = *reinterpret_cast<const float4*>(h + (size_t)row * D + k4 * 4);
            b = *reinterpret_cast<const float4*>(g_agg + (size_t)row * D + k4 * 4);
        }
        *reinterpret_cast<float4*>(s_in + e * EF_STRIDE + k4 * 4) = a;
        *reinterpret_cast<float4*>(s_hid + e * HID_STRIDE + k4 * 4) = b;
    }
    if (tid < TILE) {
        int row = r_base + tid;
        s_deg[tid] = (row < N) ? g_deg[row] : 0.f;
    }
    __syncthreads();

    const int fe = tid & 31, eg = tid >> 5;
    const int j0 = fe * 4, e0 = eg * 4;

    {
        float acc[4][4];
        float4 b2 = __ldg(reinterpret_cast<const float4*>(be2 + j0));
#pragma unroll
        for (int ee = 0; ee < 4; ++ee) {
            float dg = s_deg[e0 + ee];
            acc[ee][0] = dg * b2.x; acc[ee][1] = dg * b2.y;
            acc[ee][2] = dg * b2.z; acc[ee][3] = dg * b2.w;
        }
        mm_tile<128, HID_STRIDE>(s_hid, We2, e0, j0, acc);
        __syncthreads();
#pragma unroll
        for (int ee = 0; ee < 4; ++ee)
            *reinterpret_cast<float4*>(s_in + (e0 + ee) * EF_STRIDE + 128 + j0) =
                make_float4(acc[ee][0], acc[ee][1], acc[ee][2], acc[ee][3]);
    }
    __syncthreads();

    {
        float acc[4][4];
        load_bias(bn1, j0, acc);
        mm_tile<256, EF_STRIDE>(s_in, Wn1, e0, j0, acc);
#pragma unroll
        for (int ee = 0; ee < 4; ++ee)
            *reinterpret_cast<float4*>(s_hid + (e0 + ee) * HID_STRIDE + j0) =
                make_float4(frelu(acc[ee][0]), frelu(acc[ee][1]),
                            frelu(acc[ee][2]), frelu(acc[ee][3]));
    }
    __syncthreads();

    {
        float acc[4][4];
        load_bias(bn2, j0, acc);
        mm_tile<128, HID_STRIDE>(s_hid, Wn2, e0, j0, acc);
#pragma unroll
        for (int ee = 0; ee < 4; ++ee) {
            int row = r_base + e0 + ee;
            if (row < N)
                *reinterpret_cast<float4*>(out_h + (size_t)row * D + j0) =
                    make_float4(acc[ee][0], acc[ee][1], acc[ee][2], acc[ee][3]);
        }
    }
}

// ---------------------------------------------------------------------------
// launch
// ---------------------------------------------------------------------------
extern "C" void kernel_launch(void* const* d_in, const int* in_sizes, int n_in,
                              void* d_out, int out_size) {
    const float* h = (const float*)d_in[0];
    const float* coords = (const float*)d_in[1];
    const int* ei = (const int*)d_in[2];
    const float* We1 = (const float*)d_in[3];
    const float* be1 = (const float*)d_in[4];
    const float* We2 = (const float*)d_in[5];
    const float* be2 = (const float*)d_in[6];
    const float* Wn1 = (const float*)d_in[7];
    const float* bn1 = (const float*)d_in[8];
    const float* Wn2 = (const float*)d_in[9];
    const float* bn2 = (const float*)d_in[10];
    const float* Wc1 = (const float*)d_in[11];
    const float* bc1 = (const float*)d_in[12];
    const float* Wc2 = (const float*)d_in[13];

    int N = in_sizes[0] / D;
    int E = in_sizes[2] / 2;

    float* out_h = (float*)d_out;
    float* out_coords = out_h + (size_t)N * D;

    cudaFuncSetAttribute(edge_kernel, cudaFuncAttributeMaxDynamicSharedMemorySize,
                         EDGE_SMEM);
    cudaFuncSetAttribute(node_kernel, cudaFuncAttributeMaxDynamicSharedMemorySize,
                         NODE_SMEM_BYTES);

    prep_weights<<<D, D>>>(We2, be2, Wc1, bc1);
    prep_frags<<<16, 256>>>();
    node_prep<<<(N + TILE - 1) / TILE, NTHREADS>>>(h, We1, be1, N);
    init_kernel<<<1184, 256>>>(coords, out_coords, N);

    edge_kernel<<<(E + ETILE - 1) / ETILE, NTHREADS, EDGE_SMEM>>>(
        coords, ei, We1, Wc2, out_coords, E);

    node_kernel<<<(N + TILE - 1) / TILE, NTHREADS, NODE_SMEM_BYTES>>>(
        h, We2, be2, Wn1, bn1, Wn2, bn2, out_h, N);
}

// round 13
// speedup vs baseline: 5.0468x; 1.3879x over previous
#include <cuda_runtime.h>
#include <cuda_bf16.h>
#include <cstdint>

#define D 128
#define NTHREADS 256
#define MAXN 50000
#define ETILE 64
#define NT 64
#define A_STRIDE 136

// ---------------------------------------------------------------------------
// static scratch
// ---------------------------------------------------------------------------
__device__ float g_P1[(size_t)MAXN * D];   // h @ We1[0:128] + be1
__device__ float g_P2[(size_t)MAXN * D];   // h @ We1[128:256]
__device__ float g_Q1[(size_t)MAXN * D];   // h @ Wn1[0:128] + bn1
__device__ float g_agg[(size_t)MAXN * D];  // sum of hid per node
__device__ float g_deg[MAXN];              // degree (as float)
__device__ float g_bf[D];                  // be2 @ Wc1 + bc1
__device__ float g_bb[D];                  // be2 @ Wn1b
__device__ float g_Wf[D * D];              // We2 @ Wc1   (k-major)
__device__ float g_Wfn[D * D];             // We2 @ Wn1b  (k-major)
// B fragments in mma order: [hi/lo][nb(8)][ks(8)][lane(32)][4] u32 each
__device__ uint32_t g_frag_Wf[2 * 8 * 8 * 32 * 4];
__device__ uint32_t g_frag_Wfn[2 * 8 * 8 * 32 * 4];
__device__ uint32_t g_frag_E1a[2 * 8 * 8 * 32 * 4];
__device__ uint32_t g_frag_E1b[2 * 8 * 8 * 32 * 4];
__device__ uint32_t g_frag_N1a[2 * 8 * 8 * 32 * 4];
__device__ uint32_t g_frag_N2[2 * 8 * 8 * 32 * 4];

__device__ __forceinline__ float frelu(float x) { return x > 0.f ? x : 0.f; }

__device__ __forceinline__ uint32_t smem_u32(const void* p) {
    uint32_t a;
    asm("{ .reg .u64 t; cvta.to.shared.u64 t, %1; cvt.u32.u64 %0, t; }"
        : "=r"(a) : "l"(p));
    return a;
}

__device__ __forceinline__ void ldmat_x4(uint32_t& a0, uint32_t& a1,
                                         uint32_t& a2, uint32_t& a3,
                                         uint32_t addr) {
    asm volatile(
        "ldmatrix.sync.aligned.m8n8.x4.shared.b16 {%0,%1,%2,%3}, [%4];"
        : "=r"(a0), "=r"(a1), "=r"(a2), "=r"(a3) : "r"(addr));
}

__device__ __forceinline__ void mma_bf16(float d[4], uint32_t a0, uint32_t a1,
                                         uint32_t a2, uint32_t a3,
                                         uint32_t b0, uint32_t b1) {
    asm volatile(
        "mma.sync.aligned.m16n8k16.row.col.f32.bf16.bf16.f32 "
        "{%0,%1,%2,%3}, {%4,%5,%6,%7}, {%8,%9}, {%0,%1,%2,%3};"
        : "+f"(d[0]), "+f"(d[1]), "+f"(d[2]), "+f"(d[3])
        : "r"(a0), "r"(a1), "r"(a2), "r"(a3), "r"(b0), "r"(b1));
}

__device__ __forceinline__ void red_v4(float* dst, float4 v) {
    asm volatile(
        "red.global.add.v4.f32 [%0], {%1, %2, %3, %4};"
        :: "l"(dst), "f"(v.x), "f"(v.y), "f"(v.z), "f"(v.w) : "memory");
}

// ---------------------------------------------------------------------------
// 3-pass bf16x3 GEMM as a MACRO (textual inline: no array-typed function
// params, no address-taken locals -> no local-memory frames).
// Requires in scope: wid, lane, arow, acol8. DACC: float [4][2][4].
// ---------------------------------------------------------------------------
#define RUN_GEMM3(FRAG, AHI, ALO, DACC)                                        \
    do {                                                                       \
        _Pragma("unroll") for (int mt = 0; mt < 4; ++mt)                       \
            _Pragma("unroll") for (int nt = 0; nt < 2; ++nt)                   \
                _Pragma("unroll") for (int i = 0; i < 4; ++i)                  \
                    DACC[mt][nt][i] = 0.f;                                     \
        _Pragma("unroll") for (int pass = 0; pass < 3; ++pass) {               \
            const uint32_t abase_ = (pass == 1) ? (ALO) : (AHI);               \
            const int psel_ = (pass == 2) ? 1 : 0;                             \
            _Pragma("unroll") for (int ks = 0; ks < 8; ++ks) {                 \
                uint4 bv_ = *reinterpret_cast<const uint4*>(                   \
                    (FRAG) +                                                   \
                    ((((size_t)psel_ * 8 + wid) * 8 + ks) * 32 + lane) * 4);   \
                _Pragma("unroll") for (int mt = 0; mt < 4; ++mt) {             \
                    uint32_t addr_ = abase_ +                                  \
                        (uint32_t)((mt * 16 + arow) * (A_STRIDE * 2) +         \
                                   (ks * 16 + acol8) * 2);                     \
                    uint32_t a0_, a1_, a2_, a3_;                               \
                    ldmat_x4(a0_, a1_, a2_, a3_, addr_);                       \
                    mma_bf16(DACC[mt][0], a0_, a1_, a2_, a3_, bv_.x, bv_.y);   \
                    mma_bf16(DACC[mt][1], a0_, a1_, a2_, a3_, bv_.z, bv_.w);   \
                }                                                              \
            }                                                                  \
        }                                                                      \
    } while (0)

// store DACC (+ optional bias) to row-major fp32 out. Needs rb, nb, g, t, N.
#define STORE_OUT(OUT, BIAS, HASB, DACC)                                       \
    do {                                                                       \
        _Pragma("unroll") for (int mt = 0; mt < 4; ++mt) {                     \
            _Pragma("unroll") for (int nt = 0; nt < 2; ++nt) {                 \
                int c_ = nb + nt * 8 + t * 2;                                  \
                float b0_ = 0.f, b1_ = 0.f;                                    \
                if (HASB) {                                                    \
                    b0_ = __ldg((BIAS) + c_);                                  \
                    b1_ = __ldg((BIAS) + c_ + 1);                              \
                }                                                              \
                int r0_ = rb + mt * 16 + g;                                    \
                int r1_ = r0_ + 8;                                             \
                if (r0_ < N)                                                   \
                    *reinterpret_cast<float2*>((OUT) + (size_t)r0_ * D + c_) = \
                        make_float2(DACC[mt][nt][0] + b0_,                     \
                                    DACC[mt][nt][1] + b1_);                    \
                if (r1_ < N)                                                   \
                    *reinterpret_cast<float2*>((OUT) + (size_t)r1_ * D + c_) = \
                        make_float2(DACC[mt][nt][2] + b0_,                     \
                                    DACC[mt][nt][3] + b1_);                    \
            }                                                                  \
        }                                                                      \
    } while (0)

// ---------------------------------------------------------------------------
// prep_gemm: Wf = We2 @ Wc1, Wfn = We2 @ Wn1b (k-major fp32), bf, bb
// ---------------------------------------------------------------------------
__global__ void prep_gemm(const float* __restrict__ We2,
                          const float* __restrict__ be2,
                          const float* __restrict__ Wc1,
                          const float* __restrict__ bc1,
                          const float* __restrict__ Wn1) {
    int k = blockIdx.x;
    int j = threadIdx.x;
    const float* Wn1b = Wn1 + (size_t)128 * D;
    float a1 = 0.f, a2 = 0.f;
#pragma unroll 4
    for (int i = 0; i < D; ++i) {
        float w = We2[k * D + i];
        a1 += w * Wc1[i * D + j];
        a2 += w * Wn1b[i * D + j];
    }
    g_Wf[k * D + j] = a1;
    g_Wfn[k * D + j] = a2;
    if (k == 0) {
        float b1 = bc1[j], b2 = 0.f;
#pragma unroll 4
        for (int i = 0; i < D; ++i) {
            float b = be2[i];
            b1 += b * Wc1[i * D + j];
            b2 += b * Wn1b[i * D + j];
        }
        g_bf[j] = b1;
        g_bb[j] = b2;
    }
}

// ---------------------------------------------------------------------------
// pack_all: pack 6 weight matrices (k-major fp32) into bf16 hi/lo mma
// B-fragments. Device-side symbol resolution: no host symbol-address API.
// grid 96 x 256 = 24576 = 6 matrices x 4096 fragment slots.
// ---------------------------------------------------------------------------
__device__ __forceinline__ uint32_t wbits(const float* __restrict__ W, int c,
                                          int r, int p) {
    float v = W[c * D + r];
    __nv_bfloat16 hi = __float2bfloat16(v);
    if (p) {
        __nv_bfloat16 lo = __float2bfloat16(v - __bfloat162float(hi));
        return (uint32_t)__bfloat16_as_ushort(lo);
    }
    return (uint32_t)__bfloat16_as_ushort(hi);
}

__global__ void pack_all(const float* __restrict__ We1,
                         const float* __restrict__ Wn1,
                         const float* __restrict__ Wn2) {
    int gidx = blockIdx.x * blockDim.x + threadIdx.x;
    int m = gidx >> 12;     // matrix select 0..5
    int idx = gidx & 4095;  // fragment slot
    const float* W;
    uint32_t* dst;
    switch (m) {
        case 0: W = g_Wf; dst = g_frag_Wf; break;
        case 1: W = g_Wfn; dst = g_frag_Wfn; break;
        case 2: W = We1; dst = g_frag_E1a; break;
        case 3: W = We1 + (size_t)128 * D; dst = g_frag_E1b; break;
        case 4: W = Wn1; dst = g_frag_N1a; break;
        default: W = Wn2; dst = g_frag_N2; break;
    }
    int lane = idx & 31;
    int ks = (idx >> 5) & 7;
    int nbk = (idx >> 8) & 7;
    int p = idx >> 11;
    int g = lane >> 2, t = lane & 3;
    int col = ks * 16 + t * 2;
    int r0 = nbk * 16 + g, r1 = r0 + 8;
    uint32_t* d = dst + (size_t)idx * 4;
    d[0] = wbits(W, col, r0, p) | (wbits(W, col + 1, r0, p) << 16);
    d[1] = wbits(W, col + 8, r0, p) | (wbits(W, col + 9, r0, p) << 16);
    d[2] = wbits(W, col, r1, p) | (wbits(W, col + 1, r1, p) << 16);
    d[3] = wbits(W, col + 8, r1, p) | (wbits(W, col + 9, r1, p) << 16);
}

// ---------------------------------------------------------------------------
// init: zero agg + deg, copy coords into output coord region
// ---------------------------------------------------------------------------
__global__ void init_kernel(const float* __restrict__ coords,
                            float* __restrict__ out_coords, int N) {
    int total4 = N * (D / 4);
    for (int i = blockIdx.x * blockDim.x + threadIdx.x; i < total4;
         i += gridDim.x * blockDim.x)
        reinterpret_cast<float4*>(g_agg)[i] = make_float4(0.f, 0.f, 0.f, 0.f);
    for (int i = blockIdx.x * blockDim.x + threadIdx.x; i < N;
         i += gridDim.x * blockDim.x)
        g_deg[i] = 0.f;
    int c3 = N * 3;
    for (int i = blockIdx.x * blockDim.x + threadIdx.x; i < c3;
         i += gridDim.x * blockDim.x)
        out_coords[i] = coords[i];
}

// ---------------------------------------------------------------------------
// node_prep_mma: P1 = h@We1a + be1 ; P2 = h@We1b ; Q1 = h@Wn1a + bn1
// ---------------------------------------------------------------------------
#define NP_OFF_ALO 17408
#define NP_SMEM 34816

__global__ void __launch_bounds__(NTHREADS)
node_prep_mma(const float* __restrict__ h,
              const float* __restrict__ be1,
              const float* __restrict__ bn1, int N) {
    extern __shared__ char sm[];
    const uint32_t sbase = smem_u32(sm);
    const int tid = threadIdx.x;
    const int rb = blockIdx.x * NT;

    for (int idx = tid; idx < NT * 32; idx += NTHREADS) {
        int e = idx >> 5, k4 = idx & 31;
        int row = rb + e;
        float4 hv = make_float4(0.f, 0.f, 0.f, 0.f);
        if (row < N)
            hv = *reinterpret_cast<const float4*>(h + (size_t)row * D + k4 * 4);
        __nv_bfloat162 hp0, hp1, lp0, lp1;
        hp0.x = __float2bfloat16(hv.x);
        hp0.y = __float2bfloat16(hv.y);
        hp1.x = __float2bfloat16(hv.z);
        hp1.y = __float2bfloat16(hv.w);
        lp0.x = __float2bfloat16(hv.x - __bfloat162float(hp0.x));
        lp0.y = __float2bfloat16(hv.y - __bfloat162float(hp0.y));
        lp1.x = __float2bfloat16(hv.z - __bfloat162float(hp1.x));
        lp1.y = __float2bfloat16(hv.w - __bfloat162float(hp1.y));
        size_t boff = ((size_t)e * A_STRIDE + k4 * 4) * 2;
        *reinterpret_cast<__nv_bfloat162*>(sm + boff) = hp0;
        *reinterpret_cast<__nv_bfloat162*>(sm + boff + 4) = hp1;
        *reinterpret_cast<__nv_bfloat162*>(sm + NP_OFF_ALO + boff) = lp0;
        *reinterpret_cast<__nv_bfloat162*>(sm + NP_OFF_ALO + boff + 4) = lp1;
    }
    __syncthreads();

    const int lane = tid & 31, wid = tid >> 5;
    const int g = lane >> 2, t = lane & 3;
    const int nb = wid * 16, arow = lane & 15, acol8 = (lane >> 4) * 8;
    const uint32_t ahi = sbase, alo = sbase + NP_OFF_ALO;

    {
        float dacc[4][2][4];
        RUN_GEMM3(g_frag_E1a, ahi, alo, dacc);
        STORE_OUT(g_P1, be1, true, dacc);
    }
    {
        float dacc[4][2][4];
        RUN_GEMM3(g_frag_E1b, ahi, alo, dacc);
        STORE_OUT(g_P2, be1, false, dacc);
    }
    {
        float dacc[4][2][4];
        RUN_GEMM3(g_frag_N1a, ahi, alo, dacc);
        STORE_OUT(g_Q1, bn1, true, dacc);
    }
}

// ---------------------------------------------------------------------------
// edge kernel (byte-for-byte R10 structure; proven 2 CTA/SM, no local mem)
// ---------------------------------------------------------------------------
#define OFF_AHI 0
#define OFF_ALO 17408
#define OFF_REL 34816
#define OFF_DIST 35840
#define OFF_W 36096
#define OFF_ROW 36352
#define OFF_COL 36608
#define EDGE_SMEM 36864

__global__ void __launch_bounds__(NTHREADS, 2)
edge_kernel(const float* __restrict__ coords,
            const int* __restrict__ ei,
            const float* __restrict__ We1,
            const float* __restrict__ Wc2,
            float* __restrict__ out_coords,
            int E) {
    extern __shared__ char sm[];
    float* s_rel = reinterpret_cast<float*>(sm + OFF_REL);
    float* s_dist = reinterpret_cast<float*>(sm + OFF_DIST);
    float* s_w = reinterpret_cast<float*>(sm + OFF_W);
    int* s_row = reinterpret_cast<int*>(sm + OFF_ROW);
    int* s_col = reinterpret_cast<int*>(sm + OFF_COL);

    const uint32_t sbase = smem_u32(sm);
    const int tid = threadIdx.x;
    const int e_base = blockIdx.x * ETILE;

    if (tid < ETILE) {
        int ge = e_base + tid;
        int r = 0, c = 0;
        if (ge < E) {
            r = ei[ge];
            c = ei[E + ge];
            atomicAdd(g_deg + r, 1.0f);
        }
        s_row[tid] = r;
        s_col[tid] = c;
        float rx = coords[r * 3 + 0] - coords[c * 3 + 0];
        float ry = coords[r * 3 + 1] - coords[c * 3 + 1];
        float rz = coords[r * 3 + 2] - coords[c * 3 + 2];
        s_rel[tid * 4 + 0] = rx;
        s_rel[tid * 4 + 1] = ry;
        s_rel[tid * 4 + 2] = rz;
        s_dist[tid] = rx * rx + ry * ry + rz * rz;
        s_w[tid] = 0.f;
    }
    __syncthreads();

    {
        const int k4 = tid & 31;
        float4 w4 = __ldg(reinterpret_cast<const float4*>(
            We1 + (size_t)256 * D + k4 * 4));
        for (int idx = tid; idx < ETILE * 32; idx += NTHREADS) {
            int e = idx >> 5;
            float4 hv = make_float4(0.f, 0.f, 0.f, 0.f);
            bool live = (e_base + e < E);
            if (live) {
                int r = s_row[e], c = s_col[e];
                float4 p1 = *reinterpret_cast<const float4*>(
                    g_P1 + (size_t)r * D + k4 * 4);
                float4 p2 = *reinterpret_cast<const float4*>(
                    g_P2 + (size_t)c * D + k4 * 4);
                float d2 = s_dist[e];
                hv.x = frelu(p1.x + p2.x + d2 * w4.x);
                hv.y = frelu(p1.y + p2.y + d2 * w4.y);
                hv.z = frelu(p1.z + p2.z + d2 * w4.z);
                hv.w = frelu(p1.w + p2.w + d2 * w4.w);
                red_v4(g_agg + (size_t)s_row[e] * D + k4 * 4, hv);
            }
            __nv_bfloat162 hp0, hp1, lp0, lp1;
            hp0.x = __float2bfloat16(hv.x);
            hp0.y = __float2bfloat16(hv.y);
            hp1.x = __float2bfloat16(hv.z);
            hp1.y = __float2bfloat16(hv.w);
            lp0.x = __float2bfloat16(hv.x - __bfloat162float(hp0.x));
            lp0.y = __float2bfloat16(hv.y - __bfloat162float(hp0.y));
            lp1.x = __float2bfloat16(hv.z - __bfloat162float(hp1.x));
            lp1.y = __float2bfloat16(hv.w - __bfloat162float(hp1.y));
            size_t boff = ((size_t)e * A_STRIDE + k4 * 4) * 2;
            *reinterpret_cast<__nv_bfloat162*>(sm + OFF_AHI + boff) = hp0;
            *reinterpret_cast<__nv_bfloat162*>(sm + OFF_AHI + boff + 4) = hp1;
            *reinterpret_cast<__nv_bfloat162*>(sm + OFF_ALO + boff) = lp0;
            *reinterpret_cast<__nv_bfloat162*>(sm + OFF_ALO + boff + 4) = lp1;
        }
    }
    __syncthreads();

    const int lane = tid & 31, wid = tid >> 5;
    const int g = lane >> 2, t = lane & 3;
    const int nb = wid * 16;
    const int arow = lane & 15;
    const int acol8 = (lane >> 4) * 8;

    float dacc[4][2][4];
    RUN_GEMM3(g_frag_Wf, sbase + OFF_AHI, sbase + OFF_ALO, dacc);

    {
        float p[4][2];
#pragma unroll
        for (int mt = 0; mt < 4; ++mt) p[mt][0] = p[mt][1] = 0.f;
#pragma unroll
        for (int nt = 0; nt < 2; ++nt) {
            int j = nb + nt * 8 + t * 2;
            float bf0 = __ldg(g_bf + j), bf1 = __ldg(g_bf + j + 1);
            float w0 = __ldg(Wc2 + j), w1 = __ldg(Wc2 + j + 1);
#pragma unroll
            for (int mt = 0; mt < 4; ++mt) {
                p[mt][0] += frelu(dacc[mt][nt][0] + bf0) * w0 +
                            frelu(dacc[mt][nt][1] + bf1) * w1;
                p[mt][1] += frelu(dacc[mt][nt][2] + bf0) * w0 +
                            frelu(dacc[mt][nt][3] + bf1) * w1;
            }
        }
#pragma unroll
        for (int off = 1; off <= 2; off <<= 1)
#pragma unroll
            for (int mt = 0; mt < 4; ++mt) {
                p[mt][0] += __shfl_xor_sync(0xffffffffu, p[mt][0], off);
                p[mt][1] += __shfl_xor_sync(0xffffffffu, p[mt][1], off);
            }
        if (t == 0) {
#pragma unroll
            for (int mt = 0; mt < 4; ++mt) {
                atomicAdd(s_w + mt * 16 + g, p[mt][0]);
                atomicAdd(s_w + mt * 16 + 8 + g, p[mt][1]);
            }
        }
    }
    __syncthreads();

    if (tid < ETILE) {
        int ge = e_base + tid;
        if (ge < E) {
            float w = s_w[tid];
            int r = s_row[tid];
            atomicAdd(out_coords + r * 3 + 0, w * s_rel[tid * 4 + 0]);
            atomicAdd(out_coords + r * 3 + 1, w * s_rel[tid * 4 + 1]);
            atomicAdd(out_coords + r * 3 + 2, w * s_rel[tid * 4 + 2]);
        }
    }
}

// ---------------------------------------------------------------------------
// node_mma: hid = relu(Q1 + agg @ Wfn + deg*bb) ; out = hid @ Wn2 + bn2
// ---------------------------------------------------------------------------
#define NK_OFF_ALO 17408
#define NK_OFF_DEG 34816
#define NK_SMEM 35072

__global__ void __launch_bounds__(NTHREADS)
node_mma(const float* __restrict__ bn2, float* __restrict__ out_h, int N) {
    extern __shared__ char sm[];
    float* s_deg = reinterpret_cast<float*>(sm + NK_OFF_DEG);
    const uint32_t sbase = smem_u32(sm);
    const int tid = threadIdx.x;
    const int rb = blockIdx.x * NT;

    for (int idx = tid; idx < NT * 32; idx += NTHREADS) {
        int e = idx >> 5, k4 = idx & 31;
        int row = rb + e;
        float4 av = make_float4(0.f, 0.f, 0.f, 0.f);
        if (row < N)
            av = *reinterpret_cast<const float4*>(g_agg + (size_t)row * D + k4 * 4);
        __nv_bfloat162 hp0, hp1, lp0, lp1;
        hp0.x = __float2bfloat16(av.x);
        hp0.y = __float2bfloat16(av.y);
        hp1.x = __float2bfloat16(av.z);
        hp1.y = __float2bfloat16(av.w);
        lp0.x = __float2bfloat16(av.x - __bfloat162float(hp0.x));
        lp0.y = __float2bfloat16(av.y - __bfloat162float(hp0.y));
        lp1.x = __float2bfloat16(av.z - __bfloat162float(hp1.x));
        lp1.y = __float2bfloat16(av.w - __bfloat162float(hp1.y));
        size_t boff = ((size_t)e * A_STRIDE + k4 * 4) * 2;
        *reinterpret_cast<__nv_bfloat162*>(sm + boff) = hp0;
        *reinterpret_cast<__nv_bfloat162*>(sm + boff + 4) = hp1;
        *reinterpret_cast<__nv_bfloat162*>(sm + NK_OFF_ALO + boff) = lp0;
        *reinterpret_cast<__nv_bfloat162*>(sm + NK_OFF_ALO + boff + 4) = lp1;
    }
    if (tid < NT) {
        int row = rb + tid;
        s_deg[tid] = (row < N) ? g_deg[row] : 0.f;
    }
    __syncthreads();

    const int lane = tid & 31, wid = tid >> 5;
    const int g = lane >> 2, t = lane & 3;
    const int nb = wid * 16, arow = lane & 15, acol8 = (lane >> 4) * 8;
    const uint32_t ahi = sbase, alo = sbase + NK_OFF_ALO;

    float dacc[4][2][4];
    RUN_GEMM3(g_frag_Wfn, ahi, alo, dacc);

    __syncthreads();  // all GEMM1 A-tile reads complete before overwrite

    // hid = relu(Q1 + z + deg*bb) -> overwrite A tiles in place
#pragma unroll
    for (int mt = 0; mt < 4; ++mt) {
        float d0 = s_deg[mt * 16 + g];
        float d1 = s_deg[mt * 16 + g + 8];
        int r0 = rb + mt * 16 + g, r1 = r0 + 8;
        int rl0 = mt * 16 + g, rl1 = rl0 + 8;
#pragma unroll
        for (int nt = 0; nt < 2; ++nt) {
            int c = nb + nt * 8 + t * 2;
            float2 bb = *reinterpret_cast<const float2*>(g_bb + c);
            float q00 = 0.f, q01 = 0.f, q10 = 0.f, q11 = 0.f;
            if (r0 < N) {
                float2 q = *reinterpret_cast<const float2*>(g_Q1 + (size_t)r0 * D + c);
                q00 = q.x; q01 = q.y;
            }
            if (r1 < N) {
                float2 q = *reinterpret_cast<const float2*>(g_Q1 + (size_t)r1 * D + c);
                q10 = q.x; q11 = q.y;
            }
            float h00 = frelu(dacc[mt][nt][0] + q00 + d0 * bb.x);
            float h01 = frelu(dacc[mt][nt][1] + q01 + d0 * bb.y);
            float h10 = frelu(dacc[mt][nt][2] + q10 + d1 * bb.x);
            float h11 = frelu(dacc[mt][nt][3] + q11 + d1 * bb.y);
            __nv_bfloat162 ph0, pl0, ph1, pl1;
            ph0.x = __float2bfloat16(h00);
            ph0.y = __float2bfloat16(h01);
            pl0.x = __float2bfloat16(h00 - __bfloat162float(ph0.x));
            pl0.y = __float2bfloat16(h01 - __bfloat162float(ph0.y));
            ph1.x = __float2bfloat16(h10);
            ph1.y = __float2bfloat16(h11);
            pl1.x = __float2bfloat16(h10 - __bfloat162float(ph1.x));
            pl1.y = __float2bfloat16(h11 - __bfloat162float(ph1.y));
            size_t o0 = ((size_t)rl0 * A_STRIDE + c) * 2;
            size_t o1 = ((size_t)rl1 * A_STRIDE + c) * 2;
            *reinterpret_cast<__nv_bfloat162*>(sm + o0) = ph0;
            *reinterpret_cast<__nv_bfloat162*>(sm + NK_OFF_ALO + o0) = pl0;
            *reinterpret_cast<__nv_bfloat162*>(sm + o1) = ph1;
            *reinterpret_cast<__nv_bfloat162*>(sm + NK_OFF_ALO + o1) = pl1;
        }
    }
    __syncthreads();

    RUN_GEMM3(g_frag_N2, ahi, alo, dacc);
    STORE_OUT(out_h, bn2, true, dacc);
}

// ---------------------------------------------------------------------------
// launch
// ---------------------------------------------------------------------------
extern "C" void kernel_launch(void* const* d_in, const int* in_sizes, int n_in,
                              void* d_out, int out_size) {
    const float* h = (const float*)d_in[0];
    const float* coords = (const float*)d_in[1];
    const int* ei = (const int*)d_in[2];
    const float* We1 = (const float*)d_in[3];
    const float* be1 = (const float*)d_in[4];
    const float* We2 = (const float*)d_in[5];
    const float* be2 = (const float*)d_in[6];
    const float* Wn1 = (const float*)d_in[7];
    const float* bn1 = (const float*)d_in[8];
    const float* Wn2 = (const float*)d_in[9];
    const float* bn2 = (const float*)d_in[10];
    const float* Wc1 = (const float*)d_in[11];
    const float* bc1 = (const float*)d_in[12];
    const float* Wc2 = (const float*)d_in[13];

    int N = in_sizes[0] / D;
    int E = in_sizes[2] / 2;

    float* out_h = (float*)d_out;
    float* out_coords = out_h + (size_t)N * D;

    cudaFuncSetAttribute(edge_kernel, cudaFuncAttributeMaxDynamicSharedMemorySize,
                         EDGE_SMEM);
    cudaFuncSetAttribute(node_prep_mma, cudaFuncAttributeMaxDynamicSharedMemorySize,
                         NP_SMEM);
    cudaFuncSetAttribute(node_mma, cudaFuncAttributeMaxDynamicSharedMemorySize,
                         NK_SMEM);

    prep_gemm<<<D, D>>>(We2, be2, Wc1, bc1, Wn1);
    pack_all<<<96, 256>>>(We1, Wn1, Wn2);

    init_kernel<<<1184, 256>>>(coords, out_coords, N);

    int nblocks = (N + NT - 1) / NT;
    node_prep_mma<<<nblocks, NTHREADS, NP_SMEM>>>(h, be1, bn1, N);

    edge_kernel<<<(E + ETILE - 1) / ETILE, NTHREADS, EDGE_SMEM>>>(
        coords, ei, We1, Wc2, out_coords, E);

    node_mma<<<nblocks, NTHREADS, NK_SMEM>>>(bn2, out_h, N);
}